// round 11
// baseline (speedup 1.0000x reference)
#include <cuda_runtime.h>
#include <cuda_fp16.h>
#include <math.h>
#include <stdint.h>

#define BB    16
#define NN    4096
#define DIMK  512
#define NH    8
#define HD    64
#define INNER 512
#define MTOT  (BB * NN)   // 65536
#define BHH   (BB * NH)   // 128
#define EVW   80          // kv columns: 64 V + 1 ones(ksum) + 15 pad

// ---------------- scratch ----------------
__device__ __align__(256) __half g_Q16[(size_t)BHH * NN * HD];
__device__ __align__(256) __half g_K16[(size_t)BHH * NN * HD];
__device__ __align__(256) __half g_V16[(size_t)BHH * NN * HD];
__device__ __align__(256) __half g_X16[(size_t)MTOT * DIMK];
__device__ __align__(256) __half g_AT16[(size_t)MTOT * INNER];
__device__ __align__(256) __half g_W1[1536 * DIMK];
__device__ __align__(256) __half g_W2[INNER * INNER];
__device__ float g_kvp[8][BHH * HD * EVW];
__device__ __align__(256) __half g_kvTh[BHH * EVW * HD];   // [bh][e][d]
__device__ __align__(256) __half g_kvTl[BHH * EVW * HD];

// ---------------- helpers ----------------
__device__ __forceinline__ uint32_t smem_u32(const void* p) {
    uint32_t a;
    asm("{ .reg .u64 t; cvta.to.shared.u64 t, %1; cvt.u32.u64 %0, t; }" : "=r"(a) : "l"(p));
    return a;
}
__device__ __forceinline__ void cp16(uint32_t dst, const void* src) {
    asm volatile("cp.async.cg.shared.global [%0], [%1], 16;" ::
                 "r"(dst), "l"(__cvta_generic_to_global(src)) : "memory");
}
#define CP_COMMIT() asm volatile("cp.async.commit_group;" ::: "memory")
#define CP_WAIT(n)  asm volatile("cp.async.wait_group %0;" :: "n"(n) : "memory")

#define LDSM4(R, A)                                                              \
    asm volatile("ldmatrix.sync.aligned.m8n8.x4.shared.b16 {%0,%1,%2,%3}, [%4];" \
                 : "=r"((R)[0]), "=r"((R)[1]), "=r"((R)[2]), "=r"((R)[3])        \
                 : "r"(A))
#define LDSM4T(R, A)                                                                   \
    asm volatile("ldmatrix.sync.aligned.m8n8.x4.trans.shared.b16 {%0,%1,%2,%3}, [%4];" \
                 : "=r"((R)[0]), "=r"((R)[1]), "=r"((R)[2]), "=r"((R)[3])              \
                 : "r"(A))

__device__ __forceinline__ void mma16816(float* c, const uint32_t* a, const uint32_t* b) {
    asm volatile(
        "mma.sync.aligned.m16n8k16.row.col.f32.f16.f16.f32 "
        "{%0,%1,%2,%3}, {%4,%5,%6,%7}, {%8,%9}, {%0,%1,%2,%3};"
        : "+f"(c[0]), "+f"(c[1]), "+f"(c[2]), "+f"(c[3])
        : "r"(a[0]), "r"(a[1]), "r"(a[2]), "r"(a[3]), "r"(b[0]), "r"(b[1]));
}

// ---------------- convert fp32 -> fp16 ----------------
__global__ void k_convert(const float4* __restrict__ src, int which, int n4) {
    int i = blockIdx.x * 256 + threadIdx.x;
    if (i >= n4) return;
    float4 v = src[i];
    uint2 H;
    H.x = (uint32_t)__half_as_ushort(__float2half_rn(v.x)) |
          ((uint32_t)__half_as_ushort(__float2half_rn(v.y)) << 16);
    H.y = (uint32_t)__half_as_ushort(__float2half_rn(v.z)) |
          ((uint32_t)__half_as_ushort(__float2half_rn(v.w)) << 16);
    uint2* dst = (which == 0) ? (uint2*)g_X16 : (which == 1) ? (uint2*)g_W1 : (uint2*)g_W2;
    dst[i] = H;
}

// ---------------- fp16 GEMM, warp tile 64x64, fragment double-buffering ----
// CTA 128x128xK64, 4 warps 2(m) x 2(n), 3 smem buffers, single sync/stage.
// Per k16 slice: prefetch slice kk+1 fragments before MMAs of slice kk.
#define ROWB 144
#define ASZ  (128 * ROWB)
#define STAGE_SZ (2 * ASZ)
#define SMEM_T (3 * STAGE_SZ)

template <int GEMM_ID>
__global__ __launch_bounds__(128, 2) void k_gemm_mma(const float* __restrict__ bias,
                                                     float* __restrict__ outp) {
    extern __shared__ char smem[];
    const uint32_t sb = smem_u32(smem);
    const int tid = threadIdx.x;
    const int lane = tid & 31;
    const int wid = tid >> 5;
    const int warp_m = wid >> 1;  // 0..1 -> 64 rows
    const int warp_n = wid & 1;   // 0..1 -> 64 cols
    const int m0 = blockIdx.y * 128;
    const int n0 = blockIdx.x * 128;

    const __half* A = (GEMM_ID == 1) ? g_X16 : g_AT16;
    const __half* B = (GEMM_ID == 1) ? g_W1 : g_W2;
    const int KD = (GEMM_ID == 1) ? DIMK : INNER;

    float acc[4][8][4];
#pragma unroll
    for (int i = 0; i < 4; i++)
#pragma unroll
        for (int j = 0; j < 8; j++)
#pragma unroll
            for (int k = 0; k < 4; k++) acc[i][j][k] = 0.f;

    const int lr = tid >> 3;          // 0..15
    const int lc = tid & 7;
    const uint32_t so_base = (uint32_t)lr * ROWB + lc * 16;
    const __half* gA = A + (size_t)(m0 + lr) * KD + lc * 8;
    const __half* gB = B + (size_t)(n0 + lr) * KD + lc * 8;

    auto load_stage = [&](uint32_t st, int k0) {
#pragma unroll
        for (int i = 0; i < 8; i++) {
            uint32_t so = so_base + (uint32_t)i * 16 * ROWB;
            cp16(st + so,       gA + (size_t)(i * 16) * KD + k0);
            cp16(st + ASZ + so, gB + (size_t)(i * 16) * KD + k0);
        }
        CP_COMMIT();
    };

    load_stage(sb, 0);
    load_stage(sb + STAGE_SZ, 64);

    uint32_t cur = sb;
    uint32_t nxt2 = sb + 2 * STAGE_SZ;

    const int arow = warp_m * 64 + (lane & 15);
    const int grp = lane >> 3;
    const int brow_l = warp_n * 64 + ((grp & 2) << 2) + (lane & 7);
    const uint32_t a_off0 = (uint32_t)arow * ROWB + ((lane >> 4) * 8) * 2;
    const uint32_t b_off0 = (uint32_t)brow_l * ROWB + ((grp & 1) * 8) * 2;

    // double-buffered fragments
    uint32_t ah[2][4][4], bh[2][4][4];

#pragma unroll 1
    for (int s = 0; s < 8; s++) {
        if (s < 7) { CP_WAIT(1); } else { CP_WAIT(0); }
        __syncthreads();
        const uint32_t aT = cur, bT = cur + ASZ;

        // critical path first: fragments for slice 0
#pragma unroll
        for (int mt = 0; mt < 4; mt++)
            LDSM4(ah[0][mt], aT + a_off0 + (uint32_t)mt * 16 * ROWB);
#pragma unroll
        for (int np = 0; np < 4; np++)
            LDSM4(bh[0][np], bT + b_off0 + (uint32_t)np * 16 * ROWB);

        // then issue next-stage global loads (async, non-blocking)
        if (s < 6) {
            load_stage(nxt2, (s + 2) * 64);
            nxt2 += STAGE_SZ;
            if (nxt2 == sb + 3 * STAGE_SZ) nxt2 = sb;
        }

#pragma unroll
        for (int kk = 0; kk < 4; kk++) {
            const int cb = kk & 1;
            const int nb = cb ^ 1;
            if (kk < 3) {  // prefetch slice kk+1 fragments
#pragma unroll
                for (int mt = 0; mt < 4; mt++)
                    LDSM4(ah[nb][mt], aT + a_off0 + (uint32_t)mt * 16 * ROWB + (kk + 1) * 32);
#pragma unroll
                for (int np = 0; np < 4; np++)
                    LDSM4(bh[nb][np], bT + b_off0 + (uint32_t)np * 16 * ROWB + (kk + 1) * 32);
            }
#pragma unroll
            for (int np = 0; np < 4; np++) {
#pragma unroll
                for (int half = 0; half < 2; half++) {
                    const int nt = np * 2 + half;
                    uint32_t bhf[2] = {bh[cb][np][half * 2], bh[cb][np][half * 2 + 1]};
#pragma unroll
                    for (int mt = 0; mt < 4; mt++)
                        mma16816(acc[mt][nt], ah[cb][mt], bhf);
                }
            }
        }
        cur += STAGE_SZ;
        if (cur == sb + 3 * STAGE_SZ) cur = sb;
    }

    // ---------------- epilogue ----------------
    const int r0 = lane >> 2;
    const int c0 = (lane & 3) * 2;
#pragma unroll
    for (int mt = 0; mt < 4; mt++) {
#pragma unroll
        for (int nt = 0; nt < 8; nt++) {
            const int col = n0 + warp_n * 64 + nt * 8 + c0;
#pragma unroll
            for (int ri = 0; ri < 2; ri++) {
                const int m = m0 + warp_m * 64 + mt * 16 + r0 + ri * 8;
                float v0 = acc[mt][nt][ri * 2];
                float v1 = acc[mt][nt][ri * 2 + 1];
                if (GEMM_ID == 1) {
                    const int which = col >> 9;
                    const int h = (col >> 6) & 7;
                    const int dd = col & 63;
                    __half* dst = (which == 0) ? g_Q16 : (which == 1) ? g_K16 : g_V16;
                    if (which < 2) {
                        v0 = (v0 > 0.f) ? v0 + 1.f : expf(v0);
                        v1 = (v1 > 0.f) ? v1 + 1.f : expf(v1);
                    }
                    const int b_ = m >> 12, n_ = m & 4095;
                    *(__half2*)(dst + ((size_t)(b_ * NH + h) * NN + n_) * HD + dd) =
                        __floats2half2_rn(v0, v1);
                } else {
                    *(float2*)(outp + (size_t)m * INNER + col) =
                        make_float2(v0 + __ldg(bias + col), v1 + __ldg(bias + col + 1));
                }
            }
        }
    }
}

// ---------------- k_kv: MMA, C[64d x 80e'] = K^T [V|1|0] ----------------
#define KSTR 144
#define VSTR 176
#define KTILE (64 * KSTR)
#define VTILE (64 * VSTR)

__global__ __launch_bounds__(128) void k_kv() {
    __shared__ char sm[2 * KTILE + 2 * VTILE];
    const uint32_t sK = smem_u32(sm);
    const uint32_t sV = sK + 2 * KTILE;
    const int bh = blockIdx.x;
    const int chunk = blockIdx.y;
    const int tid = threadIdx.x;
    const int lane = tid & 31;
    const int warp = tid >> 5;

    const __half* Kg = g_K16 + ((size_t)bh * NN + chunk * 512) * HD;
    const __half* Vg = g_V16 + ((size_t)bh * NN + chunk * 512) * HD;

    {
        int r = tid & 63, buf = tid >> 6;
        uint32_t base = sV + buf * VTILE + r * VSTR + 128;
        *(uint4*)(sm + (base - sK)) = make_uint4(0x00003c00u, 0u, 0u, 0u);
        *(uint4*)(sm + (base - sK) + 16) = make_uint4(0u, 0u, 0u, 0u);
    }

    auto load = [&](int buf, int t) {
        const __half* kp = Kg + (size_t)t * 64 * HD;
        const __half* vp = Vg + (size_t)t * 64 * HD;
#pragma unroll
        for (int i = 0; i < 4; i++) {
            int idx = tid + i * 128;
            int r = idx >> 3, c = idx & 7;
            cp16(sK + buf * KTILE + r * KSTR + c * 16, kp + r * HD + c * 8);
            cp16(sV + buf * VTILE + r * VSTR + c * 16, vp + r * HD + c * 8);
        }
        CP_COMMIT();
    };

    float acc[10][4];
#pragma unroll
    for (int i = 0; i < 10; i++)
#pragma unroll
        for (int j = 0; j < 4; j++) acc[i][j] = 0.f;

    const int i7 = lane & 7;
    const int s4 = lane >> 3;
    const uint32_t aoff = (uint32_t)(i7 + ((s4 >> 1) << 3)) * KSTR +
                          (16 * warp + ((s4 & 1) << 3)) * 2;
    const uint32_t boff = (uint32_t)(i7 + ((s4 & 1) << 3)) * VSTR + ((s4 >> 1) << 3) * 2;

    load(0, 0);
#pragma unroll 1
    for (int t = 0; t < 8; t++) {
        if (t < 7) load((t + 1) & 1, t + 1);
        if (t < 7) { CP_WAIT(1); } else { CP_WAIT(0); }
        __syncthreads();
        const uint32_t kb = sK + (t & 1) * KTILE;
        const uint32_t vb = sV + (t & 1) * VTILE;
#pragma unroll
        for (int n0 = 0; n0 < 64; n0 += 16) {
            uint32_t a[4];
            LDSM4T(a, kb + aoff + n0 * KSTR);
#pragma unroll
            for (int eb = 0; eb < 5; eb++) {
                uint32_t b[4];
                LDSM4T(b, vb + boff + n0 * VSTR + eb * 32);
                mma16816(acc[2 * eb], a, b);
                mma16816(acc[2 * eb + 1], a, b + 2);
            }
        }
        __syncthreads();
    }

    float* o = g_kvp[chunk] + (size_t)bh * HD * EVW;
    const int d0 = 16 * warp + (lane >> 2);
    const int e0 = 2 * (lane & 3);
#pragma unroll
    for (int nt = 0; nt < 10; nt++) {
        int e = nt * 8 + e0;
        *(float2*)(o + d0 * EVW + e) = make_float2(acc[nt][0], acc[nt][1]);
        *(float2*)(o + (d0 + 8) * EVW + e) = make_float2(acc[nt][2], acc[nt][3]);
    }
}

// ---------------- reduce partials -> kvT hi/lo fp16 [bh][e][d] ----------------
__global__ void k_reduce() {
    int idx = blockIdx.x * 256 + threadIdx.x;
    int bh = idx / (EVW * HD);
    int r = idx % (EVW * HD);
    int e = r >> 6, d = r & 63;
    size_t in = (size_t)bh * HD * EVW + d * EVW + e;
    float s = 0.f;
#pragma unroll
    for (int p = 0; p < 8; p++) s += g_kvp[p][in];
    __half hi = __float2half_rn(s);
    g_kvTh[idx] = hi;
    g_kvTl[idx] = __float2half_rn(s - __half2float(hi));
}

// ---------------- k_attn: MMA, out = Q @ kvT^T (hi+lo), z from col 64 ----------
__global__ __launch_bounds__(128) void k_attn() {
    __shared__ char sm[64 * KSTR + 2 * EVW * KSTR];
    const uint32_t sQ = smem_u32(sm);
    const uint32_t sH = sQ + 64 * KSTR;
    const uint32_t sL = sH + EVW * KSTR;
    const int bh = blockIdx.x;
    const int tile = blockIdx.y;
    const int tid = threadIdx.x;
    const int lane = tid & 31;
    const int warp = tid >> 5;

    const __half* Qg = g_Q16 + ((size_t)bh * NN + tile * 64) * HD;
    const __half* Hg = g_kvTh + (size_t)bh * EVW * HD;
    const __half* Lg = g_kvTl + (size_t)bh * EVW * HD;

#pragma unroll
    for (int i = 0; i < 4; i++) {
        int idx = tid + i * 128;
        int r = idx >> 3, c = idx & 7;
        cp16(sQ + r * KSTR + c * 16, Qg + r * HD + c * 8);
    }
#pragma unroll
    for (int i = 0; i < 5; i++) {
        int idx = tid + i * 128;
        int r = idx >> 3, c = idx & 7;
        cp16(sH + r * KSTR + c * 16, Hg + r * HD + c * 8);
        cp16(sL + r * KSTR + c * 16, Lg + r * HD + c * 8);
    }
    CP_COMMIT();
    CP_WAIT(0);
    __syncthreads();

    float acc[10][4];
#pragma unroll
    for (int i = 0; i < 10; i++)
#pragma unroll
        for (int j = 0; j < 4; j++) acc[i][j] = 0.f;

    const int grp = lane >> 3;
    const uint32_t a_off0 = (uint32_t)(warp * 16 + (lane & 15)) * KSTR + ((lane >> 4) * 8) * 2;
    const uint32_t b_off0 = (uint32_t)(((grp & 2) << 2) + (lane & 7)) * KSTR + ((grp & 1) * 8) * 2;

#pragma unroll
    for (int kk = 0; kk < 4; kk++) {
        uint32_t a[4];
        LDSM4(a, sQ + a_off0 + kk * 32);
#pragma unroll
        for (int pass = 0; pass < 2; pass++) {
            const uint32_t base = (pass == 0) ? sH : sL;
#pragma unroll
            for (int eb = 0; eb < 5; eb++) {
                uint32_t b[4];
                LDSM4(b, base + b_off0 + (uint32_t)(16 * eb) * KSTR + kk * 32);
                mma16816(acc[2 * eb], a, b);
                mma16816(acc[2 * eb + 1], a, b + 2);
            }
        }
    }

    float d0v = __shfl_sync(0xffffffffu, acc[8][0], lane & ~3);
    float d1v = __shfl_sync(0xffffffffu, acc[8][2], lane & ~3);
    float z0 = 1.f / fmaxf(d0v, 1e-4f);
    float z1 = 1.f / fmaxf(d1v, 1e-4f);

    const int b_ = bh >> 3, h = bh & 7;
    const int n0g = tile * 64 + warp * 16 + (lane >> 2);
    __half* o = g_AT16 + ((size_t)(b_ * NN) + n0g) * INNER + h * HD;
#pragma unroll
    for (int nt = 0; nt < 8; nt++) {
        int col = nt * 8 + 2 * (lane & 3);
        *(__half2*)(o + col) = __floats2half2_rn(acc[nt][0] * z0, acc[nt][1] * z0);
        *(__half2*)(o + 8 * INNER + col) = __floats2half2_rn(acc[nt][2] * z1, acc[nt][3] * z1);
    }
}

// ---------------- launch ----------------
extern "C" void kernel_launch(void* const* d_in, const int* in_sizes, int n_in,
                              void* d_out, int out_size) {
    const float* x = (const float*)d_in[0];
    const float* W_qkv = (const float*)d_in[1];
    const float* W_out = (const float*)d_in[2];
    const float* b_out = (const float*)d_in[3];
    float* out = (float*)d_out;

    static int attr_done = 0;
    if (!attr_done) {
        cudaFuncSetAttribute((const void*)k_gemm_mma<1>,
                             cudaFuncAttributeMaxDynamicSharedMemorySize, SMEM_T);
        cudaFuncSetAttribute((const void*)k_gemm_mma<2>,
                             cudaFuncAttributeMaxDynamicSharedMemorySize, SMEM_T);
        attr_done = 1;
    }

    k_convert<<<(MTOT * DIMK / 4) / 256, 256>>>((const float4*)x, 0, MTOT * DIMK / 4);
    k_convert<<<(1536 * DIMK / 4) / 256, 256>>>((const float4*)W_qkv, 1, 1536 * DIMK / 4);
    k_convert<<<(INNER * INNER / 4) / 256, 256>>>((const float4*)W_out, 2, INNER * INNER / 4);

    dim3 g1(1536 / 128, MTOT / 128);
    k_gemm_mma<1><<<g1, 128, SMEM_T>>>(nullptr, nullptr);

    dim3 g2(BHH, 8);
    k_kv<<<g2, 128>>>();

    k_reduce<<<(BHH * EVW * HD) / 256, 256>>>();

    dim3 g3(BHH, NN / 64);
    k_attn<<<g3, 128>>>();

    dim3 g4(INNER / 128, MTOT / 128);
    k_gemm_mma<2><<<g4, 128, SMEM_T>>>(b_out, out);
}

// round 12
// speedup vs baseline: 1.0889x; 1.0889x over previous
#include <cuda_runtime.h>
#include <cuda_fp16.h>
#include <math.h>
#include <stdint.h>

#define BB    16
#define NN    4096
#define DIMK  512
#define NH    8
#define HD    64
#define INNER 512
#define MTOT  (BB * NN)   // 65536
#define BHH   (BB * NH)   // 128
#define EVW   80          // kv columns: 64 V + 1 ones(ksum) + 15 pad
#define NCHUNK 16

// ---------------- scratch ----------------
__device__ __align__(256) __half g_Q16[(size_t)BHH * NN * HD];
__device__ __align__(256) __half g_K16[(size_t)BHH * NN * HD];
__device__ __align__(256) __half g_V16[(size_t)BHH * NN * HD];
__device__ __align__(256) __half g_X16[(size_t)MTOT * DIMK];
__device__ __align__(256) __half g_AT16[(size_t)MTOT * INNER];
__device__ __align__(256) __half g_W1[1536 * DIMK];
__device__ __align__(256) __half g_W2[INNER * INNER];
__device__ float g_kvp[NCHUNK][BHH * HD * EVW];
__device__ __align__(256) __half g_kvTh[BHH * EVW * HD];   // [bh][e][d]
__device__ __align__(256) __half g_kvTl[BHH * EVW * HD];

// ---------------- helpers ----------------
__device__ __forceinline__ uint32_t smem_u32(const void* p) {
    uint32_t a;
    asm("{ .reg .u64 t; cvta.to.shared.u64 t, %1; cvt.u32.u64 %0, t; }" : "=r"(a) : "l"(p));
    return a;
}
__device__ __forceinline__ void cp16(uint32_t dst, const void* src) {
    asm volatile("cp.async.cg.shared.global [%0], [%1], 16;" ::
                 "r"(dst), "l"(__cvta_generic_to_global(src)) : "memory");
}
#define CP_COMMIT() asm volatile("cp.async.commit_group;" ::: "memory")
#define CP_WAIT(n)  asm volatile("cp.async.wait_group %0;" :: "n"(n) : "memory")

#define LDSM4(R, A)                                                              \
    asm volatile("ldmatrix.sync.aligned.m8n8.x4.shared.b16 {%0,%1,%2,%3}, [%4];" \
                 : "=r"((R)[0]), "=r"((R)[1]), "=r"((R)[2]), "=r"((R)[3])        \
                 : "r"(A))
#define LDSM4T(R, A)                                                                   \
    asm volatile("ldmatrix.sync.aligned.m8n8.x4.trans.shared.b16 {%0,%1,%2,%3}, [%4];" \
                 : "=r"((R)[0]), "=r"((R)[1]), "=r"((R)[2]), "=r"((R)[3])              \
                 : "r"(A))

__device__ __forceinline__ void mma16816(float* c, const uint32_t* a, const uint32_t* b) {
    asm volatile(
        "mma.sync.aligned.m16n8k16.row.col.f32.f16.f16.f32 "
        "{%0,%1,%2,%3}, {%4,%5,%6,%7}, {%8,%9}, {%0,%1,%2,%3};"
        : "+f"(c[0]), "+f"(c[1]), "+f"(c[2]), "+f"(c[3])
        : "r"(a[0]), "r"(a[1]), "r"(a[2]), "r"(a[3]), "r"(b[0]), "r"(b[1]));
}

// ---------------- fused convert fp32 -> fp16 (X, W1, W2 in one launch) ------
#define N4_X  (MTOT * DIMK / 4)        // 8388608
#define N4_W1 (1536 * DIMK / 4)        // 196608
#define N4_W2 (INNER * INNER / 4)      // 65536
__global__ void k_convert(const float4* __restrict__ x, const float4* __restrict__ w1,
                          const float4* __restrict__ w2) {
    int i = blockIdx.x * 256 + threadIdx.x;
    const float4* src;
    uint2* dst;
    int j = i;
    if (i < N4_X) {
        src = x; dst = (uint2*)g_X16;
    } else if (i < N4_X + N4_W1) {
        j = i - N4_X; src = w1; dst = (uint2*)g_W1;
    } else if (i < N4_X + N4_W1 + N4_W2) {
        j = i - N4_X - N4_W1; src = w2; dst = (uint2*)g_W2;
    } else {
        return;
    }
    float4 v = src[j];
    uint2 H;
    H.x = (uint32_t)__half_as_ushort(__float2half_rn(v.x)) |
          ((uint32_t)__half_as_ushort(__float2half_rn(v.y)) << 16);
    H.y = (uint32_t)__half_as_ushort(__float2half_rn(v.z)) |
          ((uint32_t)__half_as_ushort(__float2half_rn(v.w)) << 16);
    dst[j] = H;
}

// ---------------- single-pass fp16 GEMM (r9 proven: 256 thr, warp 32x64) ----
#define ROWB 144
#define ASZ  (128 * ROWB)
#define STAGE_SZ (2 * ASZ)
#define SMEM_T (3 * STAGE_SZ)

template <int GEMM_ID>
__global__ __launch_bounds__(256, 2) void k_gemm_mma(const float* __restrict__ bias,
                                                     float* __restrict__ outp) {
    extern __shared__ char smem[];
    const uint32_t sb = smem_u32(smem);
    const int tid = threadIdx.x;
    const int lane = tid & 31;
    const int wid = tid >> 5;
    const int warp_m = wid >> 1;
    const int warp_n = wid & 1;
    const int m0 = blockIdx.y * 128;
    const int n0 = blockIdx.x * 128;

    const __half* A = (GEMM_ID == 1) ? g_X16 : g_AT16;
    const __half* B = (GEMM_ID == 1) ? g_W1 : g_W2;
    const int KD = (GEMM_ID == 1) ? DIMK : INNER;

    float acc[2][8][4];
#pragma unroll
    for (int i = 0; i < 2; i++)
#pragma unroll
        for (int j = 0; j < 8; j++)
#pragma unroll
            for (int k = 0; k < 4; k++) acc[i][j][k] = 0.f;

    const int lr = tid >> 3;
    const int lc = tid & 7;
    const uint32_t so_base = (uint32_t)lr * ROWB + lc * 16;
    const __half* gA = A + (size_t)(m0 + lr) * KD + lc * 8;
    const __half* gB = B + (size_t)(n0 + lr) * KD + lc * 8;

    auto load_stage = [&](uint32_t st, int k0) {
#pragma unroll
        for (int i = 0; i < 4; i++) {
            uint32_t so = so_base + (uint32_t)i * 32 * ROWB;
            cp16(st + so,       gA + (size_t)(i * 32) * KD + k0);
            cp16(st + ASZ + so, gB + (size_t)(i * 32) * KD + k0);
        }
        CP_COMMIT();
    };

    load_stage(sb, 0);
    load_stage(sb + STAGE_SZ, 64);

    uint32_t cur = sb;
    uint32_t nxt2 = sb + 2 * STAGE_SZ;

    const int arow = warp_m * 32 + (lane & 15);
    const int grp = lane >> 3;
    const int brow_l = warp_n * 64 + ((grp & 2) << 2) + (lane & 7);
    const uint32_t a_off0 = (uint32_t)arow * ROWB + ((lane >> 4) * 8) * 2;
    const uint32_t b_off0 = (uint32_t)brow_l * ROWB + ((grp & 1) * 8) * 2;

#pragma unroll 1
    for (int s = 0; s < 8; s++) {
        if (s < 7) { CP_WAIT(1); } else { CP_WAIT(0); }
        __syncthreads();
        if (s < 6) {
            load_stage(nxt2, (s + 2) * 64);
            nxt2 += STAGE_SZ;
            if (nxt2 == sb + 3 * STAGE_SZ) nxt2 = sb;
        }
        const uint32_t aT = cur, bT = cur + ASZ;

#pragma unroll
        for (int kk = 0; kk < 4; kk++) {
            uint32_t ah[2][4];
#pragma unroll
            for (int mt = 0; mt < 2; mt++)
                LDSM4(ah[mt], aT + a_off0 + (uint32_t)mt * 16 * ROWB + kk * 32);
            uint32_t bh4[4][4];
#pragma unroll
            for (int np = 0; np < 4; np++)
                LDSM4(bh4[np], bT + b_off0 + (uint32_t)np * 16 * ROWB + kk * 32);
#pragma unroll
            for (int np = 0; np < 4; np++) {
#pragma unroll
                for (int half = 0; half < 2; half++) {
                    const int nt = np * 2 + half;
                    uint32_t bhf[2] = {bh4[np][half * 2], bh4[np][half * 2 + 1]};
#pragma unroll
                    for (int mt = 0; mt < 2; mt++)
                        mma16816(acc[mt][nt], ah[mt], bhf);
                }
            }
        }
        cur += STAGE_SZ;
        if (cur == sb + 3 * STAGE_SZ) cur = sb;
    }

    // ---------------- epilogue ----------------
    const int r0 = lane >> 2;
    const int c0 = (lane & 3) * 2;
#pragma unroll
    for (int mt = 0; mt < 2; mt++) {
#pragma unroll
        for (int nt = 0; nt < 8; nt++) {
            const int col = n0 + warp_n * 64 + nt * 8 + c0;
#pragma unroll
            for (int ri = 0; ri < 2; ri++) {
                const int m = m0 + warp_m * 32 + mt * 16 + r0 + ri * 8;
                float v0 = acc[mt][nt][ri * 2];
                float v1 = acc[mt][nt][ri * 2 + 1];
                if (GEMM_ID == 1) {
                    const int which = col >> 9;
                    const int h = (col >> 6) & 7;
                    const int dd = col & 63;
                    __half* dst = (which == 0) ? g_Q16 : (which == 1) ? g_K16 : g_V16;
                    if (which < 2) {
                        v0 = (v0 > 0.f) ? v0 + 1.f : expf(v0);
                        v1 = (v1 > 0.f) ? v1 + 1.f : expf(v1);
                    }
                    const int b_ = m >> 12, n_ = m & 4095;
                    *(__half2*)(dst + ((size_t)(b_ * NH + h) * NN + n_) * HD + dd) =
                        __floats2half2_rn(v0, v1);
                } else {
                    *(float2*)(outp + (size_t)m * INNER + col) =
                        make_float2(v0 + __ldg(bias + col), v1 + __ldg(bias + col + 1));
                }
            }
        }
    }
}

// ---------------- k_kv: MMA, C[64d x 80e'] = K^T [V|1|0], 16 chunks ----------
#define KSTR 144
#define VSTR 176
#define KTILE (64 * KSTR)
#define VTILE (64 * VSTR)
#define CHROWS (NN / NCHUNK)   // 256

__global__ __launch_bounds__(128) void k_kv() {
    __shared__ char sm[2 * KTILE + 2 * VTILE];
    const uint32_t sK = smem_u32(sm);
    const uint32_t sV = sK + 2 * KTILE;
    const int bh = blockIdx.x;
    const int chunk = blockIdx.y;
    const int tid = threadIdx.x;
    const int lane = tid & 31;
    const int warp = tid >> 5;

    const __half* Kg = g_K16 + ((size_t)bh * NN + chunk * CHROWS) * HD;
    const __half* Vg = g_V16 + ((size_t)bh * NN + chunk * CHROWS) * HD;

    {
        int r = tid & 63, buf = tid >> 6;
        uint32_t base = sV + buf * VTILE + r * VSTR + 128;
        *(uint4*)(sm + (base - sK)) = make_uint4(0x00003c00u, 0u, 0u, 0u);
        *(uint4*)(sm + (base - sK) + 16) = make_uint4(0u, 0u, 0u, 0u);
    }

    auto load = [&](int buf, int t) {
        const __half* kp = Kg + (size_t)t * 64 * HD;
        const __half* vp = Vg + (size_t)t * 64 * HD;
#pragma unroll
        for (int i = 0; i < 4; i++) {
            int idx = tid + i * 128;
            int r = idx >> 3, c = idx & 7;
            cp16(sK + buf * KTILE + r * KSTR + c * 16, kp + r * HD + c * 8);
            cp16(sV + buf * VTILE + r * VSTR + c * 16, vp + r * HD + c * 8);
        }
        CP_COMMIT();
    };

    float acc[10][4];
#pragma unroll
    for (int i = 0; i < 10; i++)
#pragma unroll
        for (int j = 0; j < 4; j++) acc[i][j] = 0.f;

    const int i7 = lane & 7;
    const int s4 = lane >> 3;
    const uint32_t aoff = (uint32_t)(i7 + ((s4 >> 1) << 3)) * KSTR +
                          (16 * warp + ((s4 & 1) << 3)) * 2;
    const uint32_t boff = (uint32_t)(i7 + ((s4 & 1) << 3)) * VSTR + ((s4 >> 1) << 3) * 2;

    load(0, 0);
#pragma unroll 1
    for (int t = 0; t < CHROWS / 64; t++) {
        if (t < CHROWS / 64 - 1) load((t + 1) & 1, t + 1);
        if (t < CHROWS / 64 - 1) { CP_WAIT(1); } else { CP_WAIT(0); }
        __syncthreads();
        const uint32_t kb = sK + (t & 1) * KTILE;
        const uint32_t vb = sV + (t & 1) * VTILE;
#pragma unroll
        for (int n0 = 0; n0 < 64; n0 += 16) {
            uint32_t a[4];
            LDSM4T(a, kb + aoff + n0 * KSTR);
#pragma unroll
            for (int eb = 0; eb < 5; eb++) {
                uint32_t b[4];
                LDSM4T(b, vb + boff + n0 * VSTR + eb * 32);
                mma16816(acc[2 * eb], a, b);
                mma16816(acc[2 * eb + 1], a, b + 2);
            }
        }
        __syncthreads();
    }

    float* o = g_kvp[chunk] + (size_t)bh * HD * EVW;
    const int d0 = 16 * warp + (lane >> 2);
    const int e0 = 2 * (lane & 3);
#pragma unroll
    for (int nt = 0; nt < 10; nt++) {
        int e = nt * 8 + e0;
        *(float2*)(o + d0 * EVW + e) = make_float2(acc[nt][0], acc[nt][1]);
        *(float2*)(o + (d0 + 8) * EVW + e) = make_float2(acc[nt][2], acc[nt][3]);
    }
}

// ---------------- reduce partials -> kvT hi/lo fp16 [bh][e][d] ----------------
__global__ void k_reduce() {
    int idx = blockIdx.x * 256 + threadIdx.x;
    int bh = idx / (EVW * HD);
    int r = idx % (EVW * HD);
    int e = r >> 6, d = r & 63;
    size_t in = (size_t)bh * HD * EVW + d * EVW + e;
    float s = 0.f;
#pragma unroll
    for (int p = 0; p < NCHUNK; p++) s += g_kvp[p][in];
    __half hi = __float2half_rn(s);
    g_kvTh[idx] = hi;
    g_kvTl[idx] = __float2half_rn(s - __half2float(hi));
}

// ---------------- k_attn: 128-row tiles, out = Q @ kvT^T (hi+lo) ----------
__global__ __launch_bounds__(128) void k_attn() {
    __shared__ char sm[128 * KSTR + 2 * EVW * KSTR];
    const uint32_t sQ = smem_u32(sm);
    const uint32_t sH = sQ + 128 * KSTR;
    const uint32_t sL = sH + EVW * KSTR;
    const int bh = blockIdx.x;
    const int tile = blockIdx.y;
    const int tid = threadIdx.x;
    const int lane = tid & 31;
    const int warp = tid >> 5;

    const __half* Qg = g_Q16 + ((size_t)bh * NN + tile * 128) * HD;
    const __half* Hg = g_kvTh + (size_t)bh * EVW * HD;
    const __half* Lg = g_kvTl + (size_t)bh * EVW * HD;

#pragma unroll
    for (int i = 0; i < 8; i++) {
        int idx = tid + i * 128;
        int r = idx >> 3, c = idx & 7;
        cp16(sQ + r * KSTR + c * 16, Qg + r * HD + c * 8);
    }
#pragma unroll
    for (int i = 0; i < 5; i++) {
        int idx = tid + i * 128;
        int r = idx >> 3, c = idx & 7;
        cp16(sH + r * KSTR + c * 16, Hg + r * HD + c * 8);
        cp16(sL + r * KSTR + c * 16, Lg + r * HD + c * 8);
    }
    CP_COMMIT();
    CP_WAIT(0);
    __syncthreads();

    float acc[2][10][4];
#pragma unroll
    for (int m = 0; m < 2; m++)
#pragma unroll
        for (int i = 0; i < 10; i++)
#pragma unroll
            for (int j = 0; j < 4; j++) acc[m][i][j] = 0.f;

    const int grp = lane >> 3;
    const uint32_t a_off0 = (uint32_t)(warp * 32 + (lane & 15)) * KSTR + ((lane >> 4) * 8) * 2;
    const uint32_t b_off0 = (uint32_t)(((grp & 2) << 2) + (lane & 7)) * KSTR + ((grp & 1) * 8) * 2;

#pragma unroll
    for (int kk = 0; kk < 4; kk++) {
        uint32_t a[2][4];
#pragma unroll
        for (int mt = 0; mt < 2; mt++)
            LDSM4(a[mt], sQ + a_off0 + (uint32_t)mt * 16 * KSTR + kk * 32);
#pragma unroll
        for (int pass = 0; pass < 2; pass++) {
            const uint32_t base = (pass == 0) ? sH : sL;
#pragma unroll
            for (int eb = 0; eb < 5; eb++) {
                uint32_t b[4];
                LDSM4(b, base + b_off0 + (uint32_t)(16 * eb) * KSTR + kk * 32);
#pragma unroll
                for (int mt = 0; mt < 2; mt++) {
                    mma16816(acc[mt][2 * eb], a[mt], b);
                    mma16816(acc[mt][2 * eb + 1], a[mt], b + 2);
                }
            }
        }
    }

    const int b_ = bh >> 3, h = bh & 7;
#pragma unroll
    for (int mt = 0; mt < 2; mt++) {
        float d0v = __shfl_sync(0xffffffffu, acc[mt][8][0], lane & ~3);
        float d1v = __shfl_sync(0xffffffffu, acc[mt][8][2], lane & ~3);
        float z0 = 1.f / fmaxf(d0v, 1e-4f);
        float z1 = 1.f / fmaxf(d1v, 1e-4f);
        const int n0g = tile * 128 + warp * 32 + mt * 16 + (lane >> 2);
        __half* o = g_AT16 + ((size_t)(b_ * NN) + n0g) * INNER + h * HD;
#pragma unroll
        for (int nt = 0; nt < 8; nt++) {
            int col = nt * 8 + 2 * (lane & 3);
            *(__half2*)(o + col) = __floats2half2_rn(acc[mt][nt][0] * z0, acc[mt][nt][1] * z0);
            *(__half2*)(o + 8 * INNER + col) =
                __floats2half2_rn(acc[mt][nt][2] * z1, acc[mt][nt][3] * z1);
        }
    }
}

// ---------------- launch ----------------
extern "C" void kernel_launch(void* const* d_in, const int* in_sizes, int n_in,
                              void* d_out, int out_size) {
    const float* x = (const float*)d_in[0];
    const float* W_qkv = (const float*)d_in[1];
    const float* W_out = (const float*)d_in[2];
    const float* b_out = (const float*)d_in[3];
    float* out = (float*)d_out;

    static int attr_done = 0;
    if (!attr_done) {
        cudaFuncSetAttribute((const void*)k_gemm_mma<1>,
                             cudaFuncAttributeMaxDynamicSharedMemorySize, SMEM_T);
        cudaFuncSetAttribute((const void*)k_gemm_mma<2>,
                             cudaFuncAttributeMaxDynamicSharedMemorySize, SMEM_T);
        attr_done = 1;
    }

    int n4_total = N4_X + N4_W1 + N4_W2;
    k_convert<<<(n4_total + 255) / 256, 256>>>((const float4*)x, (const float4*)W_qkv,
                                               (const float4*)W_out);

    dim3 g1(1536 / 128, MTOT / 128);
    k_gemm_mma<1><<<g1, 256, SMEM_T>>>(nullptr, nullptr);

    dim3 g2(BHH, NCHUNK);
    k_kv<<<g2, 128>>>();

    k_reduce<<<(BHH * EVW * HD) / 256, 256>>>();

    dim3 g3(BHH, NN / 128);
    k_attn<<<g3, 128>>>();

    dim3 g4(INNER / 128, MTOT / 128);
    k_gemm_mma<2><<<g4, 256, SMEM_T>>>(b_out, out);
}

// round 13
// speedup vs baseline: 1.1215x; 1.0300x over previous
#include <cuda_runtime.h>
#include <cuda_fp16.h>
#include <math.h>
#include <stdint.h>

#define BB    16
#define NN    4096
#define DIMK  512
#define NH    8
#define HD    64
#define INNER 512
#define MTOT  (BB * NN)   // 65536
#define BHH   (BB * NH)   // 128
#define EVW   80          // kv columns: 64 V + 1 ones(ksum) + 15 pad
#define NCHUNK 8

// ---------------- scratch ----------------
__device__ __align__(256) __half g_Q16[(size_t)BHH * NN * HD];
__device__ __align__(256) __half g_K16[(size_t)BHH * NN * HD];
__device__ __align__(256) __half g_V16[(size_t)BHH * NN * HD];
__device__ __align__(256) __half g_X16[(size_t)MTOT * DIMK];
__device__ __align__(256) __half g_AT16[(size_t)MTOT * INNER];
__device__ __align__(256) __half g_W1[1536 * DIMK];
__device__ __align__(256) __half g_W2[INNER * INNER];
__device__ float g_kvp[NCHUNK][BHH * HD * EVW];
__device__ __align__(256) __half g_kvTh[BHH * EVW * HD];   // [bh][e][d]
__device__ __align__(256) __half g_kvTl[BHH * EVW * HD];

// ---------------- helpers ----------------
__device__ __forceinline__ uint32_t smem_u32(const void* p) {
    uint32_t a;
    asm("{ .reg .u64 t; cvta.to.shared.u64 t, %1; cvt.u32.u64 %0, t; }" : "=r"(a) : "l"(p));
    return a;
}
__device__ __forceinline__ void cp16(uint32_t dst, const void* src) {
    asm volatile("cp.async.cg.shared.global [%0], [%1], 16;" ::
                 "r"(dst), "l"(__cvta_generic_to_global(src)) : "memory");
}
#define CP_COMMIT() asm volatile("cp.async.commit_group;" ::: "memory")
#define CP_WAIT(n)  asm volatile("cp.async.wait_group %0;" :: "n"(n) : "memory")

#define LDSM4(R, A)                                                              \
    asm volatile("ldmatrix.sync.aligned.m8n8.x4.shared.b16 {%0,%1,%2,%3}, [%4];" \
                 : "=r"((R)[0]), "=r"((R)[1]), "=r"((R)[2]), "=r"((R)[3])        \
                 : "r"(A))
#define LDSM4T(R, A)                                                                   \
    asm volatile("ldmatrix.sync.aligned.m8n8.x4.trans.shared.b16 {%0,%1,%2,%3}, [%4];" \
                 : "=r"((R)[0]), "=r"((R)[1]), "=r"((R)[2]), "=r"((R)[3])              \
                 : "r"(A))

__device__ __forceinline__ void mma16816(float* c, const uint32_t* a, const uint32_t* b) {
    asm volatile(
        "mma.sync.aligned.m16n8k16.row.col.f32.f16.f16.f32 "
        "{%0,%1,%2,%3}, {%4,%5,%6,%7}, {%8,%9}, {%0,%1,%2,%3};"
        : "+f"(c[0]), "+f"(c[1]), "+f"(c[2]), "+f"(c[3])
        : "r"(a[0]), "r"(a[1]), "r"(a[2]), "r"(a[3]), "r"(b[0]), "r"(b[1]));
}

// ---------------- fused convert fp32 -> fp16 ----------------
#define N4_X  (MTOT * DIMK / 4)
#define N4_W1 (1536 * DIMK / 4)
#define N4_W2 (INNER * INNER / 4)
__global__ void k_convert(const float4* __restrict__ x, const float4* __restrict__ w1,
                          const float4* __restrict__ w2) {
    int i = blockIdx.x * 256 + threadIdx.x;
    const float4* src;
    uint2* dst;
    int j = i;
    if (i < N4_X) {
        src = x; dst = (uint2*)g_X16;
    } else if (i < N4_X + N4_W1) {
        j = i - N4_X; src = w1; dst = (uint2*)g_W1;
    } else if (i < N4_X + N4_W1 + N4_W2) {
        j = i - N4_X - N4_W1; src = w2; dst = (uint2*)g_W2;
    } else {
        return;
    }
    float4 v = src[j];
    uint2 H;
    H.x = (uint32_t)__half_as_ushort(__float2half_rn(v.x)) |
          ((uint32_t)__half_as_ushort(__float2half_rn(v.y)) << 16);
    H.y = (uint32_t)__half_as_ushort(__float2half_rn(v.z)) |
          ((uint32_t)__half_as_ushort(__float2half_rn(v.w)) << 16);
    dst[j] = H;
}

// ---------------- single-pass fp16 GEMM (r9 proven: 256 thr, warp 32x64) ----
#define ROWB 144
#define ASZ  (128 * ROWB)
#define STAGE_SZ (2 * ASZ)
#define SMEM_T (3 * STAGE_SZ)

template <int GEMM_ID>
__global__ __launch_bounds__(256, 2) void k_gemm_mma(const float* __restrict__ bias,
                                                     float* __restrict__ outp) {
    extern __shared__ char smem[];
    const uint32_t sb = smem_u32(smem);
    const int tid = threadIdx.x;
    const int lane = tid & 31;
    const int wid = tid >> 5;
    const int warp_m = wid >> 1;
    const int warp_n = wid & 1;
    const int m0 = blockIdx.y * 128;
    const int n0 = blockIdx.x * 128;

    const __half* A = (GEMM_ID == 1) ? g_X16 : g_AT16;
    const __half* B = (GEMM_ID == 1) ? g_W1 : g_W2;
    const int KD = (GEMM_ID == 1) ? DIMK : INNER;

    float acc[2][8][4];
#pragma unroll
    for (int i = 0; i < 2; i++)
#pragma unroll
        for (int j = 0; j < 8; j++)
#pragma unroll
            for (int k = 0; k < 4; k++) acc[i][j][k] = 0.f;

    const int lr = tid >> 3;
    const int lc = tid & 7;
    const uint32_t so_base = (uint32_t)lr * ROWB + lc * 16;
    const __half* gA = A + (size_t)(m0 + lr) * KD + lc * 8;
    const __half* gB = B + (size_t)(n0 + lr) * KD + lc * 8;

    auto load_stage = [&](uint32_t st, int k0) {
#pragma unroll
        for (int i = 0; i < 4; i++) {
            uint32_t so = so_base + (uint32_t)i * 32 * ROWB;
            cp16(st + so,       gA + (size_t)(i * 32) * KD + k0);
            cp16(st + ASZ + so, gB + (size_t)(i * 32) * KD + k0);
        }
        CP_COMMIT();
    };

    load_stage(sb, 0);
    load_stage(sb + STAGE_SZ, 64);

    uint32_t cur = sb;
    uint32_t nxt2 = sb + 2 * STAGE_SZ;

    const int arow = warp_m * 32 + (lane & 15);
    const int grp = lane >> 3;
    const int brow_l = warp_n * 64 + ((grp & 2) << 2) + (lane & 7);
    const uint32_t a_off0 = (uint32_t)arow * ROWB + ((lane >> 4) * 8) * 2;
    const uint32_t b_off0 = (uint32_t)brow_l * ROWB + ((grp & 1) * 8) * 2;

#pragma unroll 1
    for (int s = 0; s < 8; s++) {
        if (s < 7) { CP_WAIT(1); } else { CP_WAIT(0); }
        __syncthreads();
        if (s < 6) {
            load_stage(nxt2, (s + 2) * 64);
            nxt2 += STAGE_SZ;
            if (nxt2 == sb + 3 * STAGE_SZ) nxt2 = sb;
        }
        const uint32_t aT = cur, bT = cur + ASZ;

#pragma unroll
        for (int kk = 0; kk < 4; kk++) {
            uint32_t ah[2][4];
#pragma unroll
            for (int mt = 0; mt < 2; mt++)
                LDSM4(ah[mt], aT + a_off0 + (uint32_t)mt * 16 * ROWB + kk * 32);
            uint32_t bh4[4][4];
#pragma unroll
            for (int np = 0; np < 4; np++)
                LDSM4(bh4[np], bT + b_off0 + (uint32_t)np * 16 * ROWB + kk * 32);
#pragma unroll
            for (int np = 0; np < 4; np++) {
#pragma unroll
                for (int half = 0; half < 2; half++) {
                    const int nt = np * 2 + half;
                    uint32_t bhf[2] = {bh4[np][half * 2], bh4[np][half * 2 + 1]};
#pragma unroll
                    for (int mt = 0; mt < 2; mt++)
                        mma16816(acc[mt][nt], ah[mt], bhf);
                }
            }
        }
        cur += STAGE_SZ;
        if (cur == sb + 3 * STAGE_SZ) cur = sb;
    }

    // ---------------- epilogue ----------------
    const int r0 = lane >> 2;
    const int c0 = (lane & 3) * 2;
#pragma unroll
    for (int mt = 0; mt < 2; mt++) {
#pragma unroll
        for (int nt = 0; nt < 8; nt++) {
            const int col = n0 + warp_n * 64 + nt * 8 + c0;
#pragma unroll
            for (int ri = 0; ri < 2; ri++) {
                const int m = m0 + warp_m * 32 + mt * 16 + r0 + ri * 8;
                float v0 = acc[mt][nt][ri * 2];
                float v1 = acc[mt][nt][ri * 2 + 1];
                if (GEMM_ID == 1) {
                    const int which = col >> 9;
                    const int h = (col >> 6) & 7;
                    const int dd = col & 63;
                    __half* dst = (which == 0) ? g_Q16 : (which == 1) ? g_K16 : g_V16;
                    if (which < 2) {
                        v0 = (v0 > 0.f) ? v0 + 1.f : expf(v0);
                        v1 = (v1 > 0.f) ? v1 + 1.f : expf(v1);
                    }
                    const int b_ = m >> 12, n_ = m & 4095;
                    *(__half2*)(dst + ((size_t)(b_ * NH + h) * NN + n_) * HD + dd) =
                        __floats2half2_rn(v0, v1);
                } else {
                    *(float2*)(outp + (size_t)m * INNER + col) =
                        make_float2(v0 + __ldg(bias + col), v1 + __ldg(bias + col + 1));
                }
            }
        }
    }
}

// ---------------- k_kv: MMA, C[64d x 80e'] = K^T [V|1|0], 8 chunks ----------
#define KSTR 144
#define VSTR 176
#define KTILE (64 * KSTR)
#define VTILE (64 * VSTR)
#define CHROWS (NN / NCHUNK)   // 512

__global__ __launch_bounds__(128) void k_kv() {
    __shared__ char sm[2 * KTILE + 2 * VTILE];
    const uint32_t sK = smem_u32(sm);
    const uint32_t sV = sK + 2 * KTILE;
    const int bh = blockIdx.x;
    const int chunk = blockIdx.y;
    const int tid = threadIdx.x;
    const int lane = tid & 31;
    const int warp = tid >> 5;

    const __half* Kg = g_K16 + ((size_t)bh * NN + chunk * CHROWS) * HD;
    const __half* Vg = g_V16 + ((size_t)bh * NN + chunk * CHROWS) * HD;

    {
        int r = tid & 63, buf = tid >> 6;
        uint32_t base = sV + buf * VTILE + r * VSTR + 128;
        *(uint4*)(sm + (base - sK)) = make_uint4(0x00003c00u, 0u, 0u, 0u);
        *(uint4*)(sm + (base - sK) + 16) = make_uint4(0u, 0u, 0u, 0u);
    }

    auto load = [&](int buf, int t) {
        const __half* kp = Kg + (size_t)t * 64 * HD;
        const __half* vp = Vg + (size_t)t * 64 * HD;
#pragma unroll
        for (int i = 0; i < 4; i++) {
            int idx = tid + i * 128;
            int r = idx >> 3, c = idx & 7;
            cp16(sK + buf * KTILE + r * KSTR + c * 16, kp + r * HD + c * 8);
            cp16(sV + buf * VTILE + r * VSTR + c * 16, vp + r * HD + c * 8);
        }
        CP_COMMIT();
    };

    float acc[10][4];
#pragma unroll
    for (int i = 0; i < 10; i++)
#pragma unroll
        for (int j = 0; j < 4; j++) acc[i][j] = 0.f;

    const int i7 = lane & 7;
    const int s4 = lane >> 3;
    const uint32_t aoff = (uint32_t)(i7 + ((s4 >> 1) << 3)) * KSTR +
                          (16 * warp + ((s4 & 1) << 3)) * 2;
    const uint32_t boff = (uint32_t)(i7 + ((s4 & 1) << 3)) * VSTR + ((s4 >> 1) << 3) * 2;

    load(0, 0);
#pragma unroll 1
    for (int t = 0; t < CHROWS / 64; t++) {
        if (t < CHROWS / 64 - 1) load((t + 1) & 1, t + 1);
        if (t < CHROWS / 64 - 1) { CP_WAIT(1); } else { CP_WAIT(0); }
        __syncthreads();
        const uint32_t kb = sK + (t & 1) * KTILE;
        const uint32_t vb = sV + (t & 1) * VTILE;
#pragma unroll
        for (int n0 = 0; n0 < 64; n0 += 16) {
            uint32_t a[4];
            LDSM4T(a, kb + aoff + n0 * KSTR);
#pragma unroll
            for (int eb = 0; eb < 5; eb++) {
                uint32_t b[4];
                LDSM4T(b, vb + boff + n0 * VSTR + eb * 32);
                mma16816(acc[2 * eb], a, b);
                mma16816(acc[2 * eb + 1], a, b + 2);
            }
        }
        __syncthreads();
    }

    float* o = g_kvp[chunk] + (size_t)bh * HD * EVW;
    const int d0 = 16 * warp + (lane >> 2);
    const int e0 = 2 * (lane & 3);
#pragma unroll
    for (int nt = 0; nt < 10; nt++) {
        int e = nt * 8 + e0;
        *(float2*)(o + d0 * EVW + e) = make_float2(acc[nt][0], acc[nt][1]);
        *(float2*)(o + (d0 + 8) * EVW + e) = make_float2(acc[nt][2], acc[nt][3]);
    }
}

// ---------------- reduce partials -> kvT hi/lo [bh][e][d], smem transpose ----
// one CTA per bh: coalesced reads of [d][e] layout, transpose in smem,
// coalesced-ish writes of [e][d] fp16.
__global__ __launch_bounds__(256) void k_reduce() {
    __shared__ float buf[HD * EVW];   // 20 KB
    const int bh = blockIdx.x;
    const int tid = threadIdx.x;
    const size_t base = (size_t)bh * HD * EVW;
#pragma unroll
    for (int i = 0; i < (HD * EVW) / 256; i++) {
        int idx = tid + i * 256;      // in-layout offset (coalesced)
        float s = 0.f;
#pragma unroll
        for (int p = 0; p < NCHUNK; p++) s += g_kvp[p][base + idx];
        buf[idx] = s;
    }
    __syncthreads();
    __half* oh = g_kvTh + (size_t)bh * EVW * HD;
    __half* ol = g_kvTl + (size_t)bh * EVW * HD;
#pragma unroll
    for (int i = 0; i < (HD * EVW) / 256; i++) {
        int idx = tid + i * 256;      // out-layout offset: e*HD + d
        int e = idx >> 6, d = idx & 63;
        float s = buf[d * EVW + e];
        __half hi = __float2half_rn(s);
        oh[idx] = hi;
        ol[idx] = __float2half_rn(s - __half2float(hi));
    }
}

// ---------------- k_attn: 128-row tiles, out = Q @ kvT^T (hi+lo) ----------
__global__ __launch_bounds__(128) void k_attn() {
    __shared__ char sm[128 * KSTR + 2 * EVW * KSTR];
    const uint32_t sQ = smem_u32(sm);
    const uint32_t sH = sQ + 128 * KSTR;
    const uint32_t sL = sH + EVW * KSTR;
    const int bh = blockIdx.x;
    const int tile = blockIdx.y;
    const int tid = threadIdx.x;
    const int lane = tid & 31;
    const int warp = tid >> 5;

    const __half* Qg = g_Q16 + ((size_t)bh * NN + tile * 128) * HD;
    const __half* Hg = g_kvTh + (size_t)bh * EVW * HD;
    const __half* Lg = g_kvTl + (size_t)bh * EVW * HD;

#pragma unroll
    for (int i = 0; i < 8; i++) {
        int idx = tid + i * 128;
        int r = idx >> 3, c = idx & 7;
        cp16(sQ + r * KSTR + c * 16, Qg + r * HD + c * 8);
    }
#pragma unroll
    for (int i = 0; i < 5; i++) {
        int idx = tid + i * 128;
        int r = idx >> 3, c = idx & 7;
        cp16(sH + r * KSTR + c * 16, Hg + r * HD + c * 8);
        cp16(sL + r * KSTR + c * 16, Lg + r * HD + c * 8);
    }
    CP_COMMIT();
    CP_WAIT(0);
    __syncthreads();

    float acc[2][10][4];
#pragma unroll
    for (int m = 0; m < 2; m++)
#pragma unroll
        for (int i = 0; i < 10; i++)
#pragma unroll
            for (int j = 0; j < 4; j++) acc[m][i][j] = 0.f;

    const int grp = lane >> 3;
    const uint32_t a_off0 = (uint32_t)(warp * 32 + (lane & 15)) * KSTR + ((lane >> 4) * 8) * 2;
    const uint32_t b_off0 = (uint32_t)(((grp & 2) << 2) + (lane & 7)) * KSTR + ((grp & 1) * 8) * 2;

#pragma unroll
    for (int kk = 0; kk < 4; kk++) {
        uint32_t a[2][4];
#pragma unroll
        for (int mt = 0; mt < 2; mt++)
            LDSM4(a[mt], sQ + a_off0 + (uint32_t)mt * 16 * KSTR + kk * 32);
#pragma unroll
        for (int pass = 0; pass < 2; pass++) {
            const uint32_t base = (pass == 0) ? sH : sL;
#pragma unroll
            for (int eb = 0; eb < 5; eb++) {
                uint32_t b[4];
                LDSM4(b, base + b_off0 + (uint32_t)(16 * eb) * KSTR + kk * 32);
#pragma unroll
                for (int mt = 0; mt < 2; mt++) {
                    mma16816(acc[mt][2 * eb], a[mt], b);
                    mma16816(acc[mt][2 * eb + 1], a[mt], b + 2);
                }
            }
        }
    }

    const int b_ = bh >> 3, h = bh & 7;
#pragma unroll
    for (int mt = 0; mt < 2; mt++) {
        float d0v = __shfl_sync(0xffffffffu, acc[mt][8][0], lane & ~3);
        float d1v = __shfl_sync(0xffffffffu, acc[mt][8][2], lane & ~3);
        float z0 = 1.f / fmaxf(d0v, 1e-4f);
        float z1 = 1.f / fmaxf(d1v, 1e-4f);
        const int n0g = tile * 128 + warp * 32 + mt * 16 + (lane >> 2);
        __half* o = g_AT16 + ((size_t)(b_ * NN) + n0g) * INNER + h * HD;
#pragma unroll
        for (int nt = 0; nt < 8; nt++) {
            int col = nt * 8 + 2 * (lane & 3);
            *(__half2*)(o + col) = __floats2half2_rn(acc[mt][nt][0] * z0, acc[mt][nt][1] * z0);
            *(__half2*)(o + 8 * INNER + col) =
                __floats2half2_rn(acc[mt][nt][2] * z1, acc[mt][nt][3] * z1);
        }
    }
}

// ---------------- launch ----------------
extern "C" void kernel_launch(void* const* d_in, const int* in_sizes, int n_in,
                              void* d_out, int out_size) {
    const float* x = (const float*)d_in[0];
    const float* W_qkv = (const float*)d_in[1];
    const float* W_out = (const float*)d_in[2];
    const float* b_out = (const float*)d_in[3];
    float* out = (float*)d_out;

    static int attr_done = 0;
    if (!attr_done) {
        cudaFuncSetAttribute((const void*)k_gemm_mma<1>,
                             cudaFuncAttributeMaxDynamicSharedMemorySize, SMEM_T);
        cudaFuncSetAttribute((const void*)k_gemm_mma<2>,
                             cudaFuncAttributeMaxDynamicSharedMemorySize, SMEM_T);
        attr_done = 1;
    }

    int n4_total = N4_X + N4_W1 + N4_W2;
    k_convert<<<(n4_total + 255) / 256, 256>>>((const float4*)x, (const float4*)W_qkv,
                                               (const float4*)W_out);

    dim3 g1(1536 / 128, MTOT / 128);
    k_gemm_mma<1><<<g1, 256, SMEM_T>>>(nullptr, nullptr);

    dim3 g2(BHH, NCHUNK);
    k_kv<<<g2, 128>>>();

    k_reduce<<<BHH, 256>>>();

    dim3 g3(BHH, NN / 128);
    k_attn<<<g3, 128>>>();

    dim3 g4(INNER / 128, MTOT / 128);
    k_gemm_mma<2><<<g4, 256, SMEM_T>>>(b_out, out);
}

// round 14
// speedup vs baseline: 1.1514x; 1.0266x over previous
#include <cuda_runtime.h>
#include <cuda_fp16.h>
#include <math.h>
#include <stdint.h>

#define BB    16
#define NN    4096
#define DIMK  512
#define NH    8
#define HD    64
#define INNER 512
#define MTOT  (BB * NN)   // 65536
#define BHH   (BB * NH)   // 128
#define EVW   80          // kv columns: 64 V + 1 ones(ksum) + 15 pad
#define NCHUNK 8

// ---------------- scratch ----------------
__device__ __align__(256) __half g_Q16[(size_t)BHH * NN * HD];
__device__ __align__(256) __half g_K16[(size_t)BHH * NN * HD];
__device__ __align__(256) __half g_V16[(size_t)BHH * NN * HD];
__device__ __align__(256) __half g_X16[(size_t)MTOT * DIMK];
__device__ __align__(256) __half g_AT16[(size_t)MTOT * INNER];
__device__ __align__(256) __half g_W1[1536 * DIMK];
__device__ __align__(256) __half g_W2[INNER * INNER];
__device__ float g_kvp[NCHUNK][BHH * HD * EVW];
__device__ __align__(256) __half g_kvTh[BHH * EVW * HD];   // [bh][e][d]

// ---------------- helpers ----------------
__device__ __forceinline__ uint32_t smem_u32(const void* p) {
    uint32_t a;
    asm("{ .reg .u64 t; cvta.to.shared.u64 t, %1; cvt.u32.u64 %0, t; }" : "=r"(a) : "l"(p));
    return a;
}
__device__ __forceinline__ void cp16(uint32_t dst, const void* src) {
    asm volatile("cp.async.cg.shared.global [%0], [%1], 16;" ::
                 "r"(dst), "l"(__cvta_generic_to_global(src)) : "memory");
}
#define CP_COMMIT() asm volatile("cp.async.commit_group;" ::: "memory")
#define CP_WAIT(n)  asm volatile("cp.async.wait_group %0;" :: "n"(n) : "memory")

#define LDSM4(R, A)                                                              \
    asm volatile("ldmatrix.sync.aligned.m8n8.x4.shared.b16 {%0,%1,%2,%3}, [%4];" \
                 : "=r"((R)[0]), "=r"((R)[1]), "=r"((R)[2]), "=r"((R)[3])        \
                 : "r"(A))
#define LDSM4T(R, A)                                                                   \
    asm volatile("ldmatrix.sync.aligned.m8n8.x4.trans.shared.b16 {%0,%1,%2,%3}, [%4];" \
                 : "=r"((R)[0]), "=r"((R)[1]), "=r"((R)[2]), "=r"((R)[3])              \
                 : "r"(A))

__device__ __forceinline__ void mma16816(float* c, const uint32_t* a, const uint32_t* b) {
    asm volatile(
        "mma.sync.aligned.m16n8k16.row.col.f32.f16.f16.f32 "
        "{%0,%1,%2,%3}, {%4,%5,%6,%7}, {%8,%9}, {%0,%1,%2,%3};"
        : "+f"(c[0]), "+f"(c[1]), "+f"(c[2]), "+f"(c[3])
        : "r"(a[0]), "r"(a[1]), "r"(a[2]), "r"(a[3]), "r"(b[0]), "r"(b[1]));
}

// ---------------- fused convert fp32 -> fp16 ----------------
#define N4_X  (MTOT * DIMK / 4)
#define N4_W1 (1536 * DIMK / 4)
#define N4_W2 (INNER * INNER / 4)
__global__ void k_convert(const float4* __restrict__ x, const float4* __restrict__ w1,
                          const float4* __restrict__ w2) {
    int i = blockIdx.x * 256 + threadIdx.x;
    const float4* src;
    uint2* dst;
    int j = i;
    if (i < N4_X) {
        src = x; dst = (uint2*)g_X16;
    } else if (i < N4_X + N4_W1) {
        j = i - N4_X; src = w1; dst = (uint2*)g_W1;
    } else if (i < N4_X + N4_W1 + N4_W2) {
        j = i - N4_X - N4_W1; src = w2; dst = (uint2*)g_W2;
    } else {
        return;
    }
    float4 v = src[j];
    uint2 H;
    H.x = (uint32_t)__half_as_ushort(__float2half_rn(v.x)) |
          ((uint32_t)__half_as_ushort(__float2half_rn(v.y)) << 16);
    H.y = (uint32_t)__half_as_ushort(__float2half_rn(v.z)) |
          ((uint32_t)__half_as_ushort(__float2half_rn(v.w)) << 16);
    dst[j] = H;
}

// ---------------- single-pass fp16 GEMM (r9 proven: 256 thr, warp 32x64) ----
#define ROWB 144
#define ASZ  (128 * ROWB)
#define STAGE_SZ (2 * ASZ)
#define SMEM_T (3 * STAGE_SZ)

template <int GEMM_ID>
__global__ __launch_bounds__(256, 2) void k_gemm_mma(const float* __restrict__ bias,
                                                     float* __restrict__ outp) {
    extern __shared__ char smem[];
    const uint32_t sb = smem_u32(smem);
    const int tid = threadIdx.x;
    const int lane = tid & 31;
    const int wid = tid >> 5;
    const int warp_m = wid >> 1;
    const int warp_n = wid & 1;
    const int m0 = blockIdx.y * 128;
    const int n0 = blockIdx.x * 128;

    const __half* A = (GEMM_ID == 1) ? g_X16 : g_AT16;
    const __half* B = (GEMM_ID == 1) ? g_W1 : g_W2;
    const int KD = (GEMM_ID == 1) ? DIMK : INNER;

    float acc[2][8][4];
#pragma unroll
    for (int i = 0; i < 2; i++)
#pragma unroll
        for (int j = 0; j < 8; j++)
#pragma unroll
            for (int k = 0; k < 4; k++) acc[i][j][k] = 0.f;

    const int lr = tid >> 3;
    const int lc = tid & 7;
    const uint32_t so_base = (uint32_t)lr * ROWB + lc * 16;
    const __half* gA = A + (size_t)(m0 + lr) * KD + lc * 8;
    const __half* gB = B + (size_t)(n0 + lr) * KD + lc * 8;

    auto load_stage = [&](uint32_t st, int k0) {
#pragma unroll
        for (int i = 0; i < 4; i++) {
            uint32_t so = so_base + (uint32_t)i * 32 * ROWB;
            cp16(st + so,       gA + (size_t)(i * 32) * KD + k0);
            cp16(st + ASZ + so, gB + (size_t)(i * 32) * KD + k0);
        }
        CP_COMMIT();
    };

    load_stage(sb, 0);
    load_stage(sb + STAGE_SZ, 64);

    uint32_t cur = sb;
    uint32_t nxt2 = sb + 2 * STAGE_SZ;

    const int arow = warp_m * 32 + (lane & 15);
    const int grp = lane >> 3;
    const int brow_l = warp_n * 64 + ((grp & 2) << 2) + (lane & 7);
    const uint32_t a_off0 = (uint32_t)arow * ROWB + ((lane >> 4) * 8) * 2;
    const uint32_t b_off0 = (uint32_t)brow_l * ROWB + ((grp & 1) * 8) * 2;

#pragma unroll 1
    for (int s = 0; s < 8; s++) {
        if (s < 7) { CP_WAIT(1); } else { CP_WAIT(0); }
        __syncthreads();
        if (s < 6) {
            load_stage(nxt2, (s + 2) * 64);
            nxt2 += STAGE_SZ;
            if (nxt2 == sb + 3 * STAGE_SZ) nxt2 = sb;
        }
        const uint32_t aT = cur, bT = cur + ASZ;

#pragma unroll
        for (int kk = 0; kk < 4; kk++) {
            uint32_t ah[2][4];
#pragma unroll
            for (int mt = 0; mt < 2; mt++)
                LDSM4(ah[mt], aT + a_off0 + (uint32_t)mt * 16 * ROWB + kk * 32);
            uint32_t bh4[4][4];
#pragma unroll
            for (int np = 0; np < 4; np++)
                LDSM4(bh4[np], bT + b_off0 + (uint32_t)np * 16 * ROWB + kk * 32);
#pragma unroll
            for (int np = 0; np < 4; np++) {
#pragma unroll
                for (int half = 0; half < 2; half++) {
                    const int nt = np * 2 + half;
                    uint32_t bhf[2] = {bh4[np][half * 2], bh4[np][half * 2 + 1]};
#pragma unroll
                    for (int mt = 0; mt < 2; mt++)
                        mma16816(acc[mt][nt], ah[mt], bhf);
                }
            }
        }
        cur += STAGE_SZ;
        if (cur == sb + 3 * STAGE_SZ) cur = sb;
    }

    // ---------------- epilogue ----------------
    const int r0 = lane >> 2;
    const int c0 = (lane & 3) * 2;
#pragma unroll
    for (int mt = 0; mt < 2; mt++) {
#pragma unroll
        for (int nt = 0; nt < 8; nt++) {
            const int col = n0 + warp_n * 64 + nt * 8 + c0;
#pragma unroll
            for (int ri = 0; ri < 2; ri++) {
                const int m = m0 + warp_m * 32 + mt * 16 + r0 + ri * 8;
                float v0 = acc[mt][nt][ri * 2];
                float v1 = acc[mt][nt][ri * 2 + 1];
                if (GEMM_ID == 1) {
                    const int which = col >> 9;
                    const int h = (col >> 6) & 7;
                    const int dd = col & 63;
                    __half* dst = (which == 0) ? g_Q16 : (which == 1) ? g_K16 : g_V16;
                    if (which < 2) {
                        v0 = (v0 > 0.f) ? v0 + 1.f : expf(v0);
                        v1 = (v1 > 0.f) ? v1 + 1.f : expf(v1);
                    }
                    const int b_ = m >> 12, n_ = m & 4095;
                    *(__half2*)(dst + ((size_t)(b_ * NH + h) * NN + n_) * HD + dd) =
                        __floats2half2_rn(v0, v1);
                } else {
                    *(float2*)(outp + (size_t)m * INNER + col) =
                        make_float2(v0 + __ldg(bias + col), v1 + __ldg(bias + col + 1));
                }
            }
        }
    }
}

// ---------------- k_kv: MMA, C[64d x 80e'] = K^T [V|1|0], 8 chunks ----------
#define KSTR 144
#define VSTR 176
#define KTILE (64 * KSTR)
#define VTILE (64 * VSTR)
#define CHROWS (NN / NCHUNK)   // 512

__global__ __launch_bounds__(128) void k_kv() {
    __shared__ char sm[2 * KTILE + 2 * VTILE];
    const uint32_t sK = smem_u32(sm);
    const uint32_t sV = sK + 2 * KTILE;
    const int bh = blockIdx.x;
    const int chunk = blockIdx.y;
    const int tid = threadIdx.x;
    const int lane = tid & 31;
    const int warp = tid >> 5;

    const __half* Kg = g_K16 + ((size_t)bh * NN + chunk * CHROWS) * HD;
    const __half* Vg = g_V16 + ((size_t)bh * NN + chunk * CHROWS) * HD;

    {
        int r = tid & 63, buf = tid >> 6;
        uint32_t base = sV + buf * VTILE + r * VSTR + 128;
        *(uint4*)(sm + (base - sK)) = make_uint4(0x00003c00u, 0u, 0u, 0u);
        *(uint4*)(sm + (base - sK) + 16) = make_uint4(0u, 0u, 0u, 0u);
    }

    auto load = [&](int buf, int t) {
        const __half* kp = Kg + (size_t)t * 64 * HD;
        const __half* vp = Vg + (size_t)t * 64 * HD;
#pragma unroll
        for (int i = 0; i < 4; i++) {
            int idx = tid + i * 128;
            int r = idx >> 3, c = idx & 7;
            cp16(sK + buf * KTILE + r * KSTR + c * 16, kp + r * HD + c * 8);
            cp16(sV + buf * VTILE + r * VSTR + c * 16, vp + r * HD + c * 8);
        }
        CP_COMMIT();
    };

    float acc[10][4];
#pragma unroll
    for (int i = 0; i < 10; i++)
#pragma unroll
        for (int j = 0; j < 4; j++) acc[i][j] = 0.f;

    const int i7 = lane & 7;
    const int s4 = lane >> 3;
    const uint32_t aoff = (uint32_t)(i7 + ((s4 >> 1) << 3)) * KSTR +
                          (16 * warp + ((s4 & 1) << 3)) * 2;
    const uint32_t boff = (uint32_t)(i7 + ((s4 & 1) << 3)) * VSTR + ((s4 >> 1) << 3) * 2;

    load(0, 0);
#pragma unroll 1
    for (int t = 0; t < CHROWS / 64; t++) {
        if (t < CHROWS / 64 - 1) load((t + 1) & 1, t + 1);
        if (t < CHROWS / 64 - 1) { CP_WAIT(1); } else { CP_WAIT(0); }
        __syncthreads();
        const uint32_t kb = sK + (t & 1) * KTILE;
        const uint32_t vb = sV + (t & 1) * VTILE;
#pragma unroll
        for (int n0 = 0; n0 < 64; n0 += 16) {
            uint32_t a[4];
            LDSM4T(a, kb + aoff + n0 * KSTR);
#pragma unroll
            for (int eb = 0; eb < 5; eb++) {
                uint32_t b[4];
                LDSM4T(b, vb + boff + n0 * VSTR + eb * 32);
                mma16816(acc[2 * eb], a, b);
                mma16816(acc[2 * eb + 1], a, b + 2);
            }
        }
        __syncthreads();
    }

    float* o = g_kvp[chunk] + (size_t)bh * HD * EVW;
    const int d0 = 16 * warp + (lane >> 2);
    const int e0 = 2 * (lane & 3);
#pragma unroll
    for (int nt = 0; nt < 10; nt++) {
        int e = nt * 8 + e0;
        *(float2*)(o + d0 * EVW + e) = make_float2(acc[nt][0], acc[nt][1]);
        *(float2*)(o + (d0 + 8) * EVW + e) = make_float2(acc[nt][2], acc[nt][3]);
    }
}

// ---------------- reduce partials -> kvT fp16 [bh][e][d], 4-way d split ------
__global__ __launch_bounds__(256) void k_reduce() {
    __shared__ float buf[16 * EVW];   // 5 KB
    const int bh = blockIdx.x;
    const int q = blockIdx.y;         // d-quarter 0..3
    const int tid = threadIdx.x;
    const size_t base = (size_t)bh * HD * EVW + (size_t)q * 16 * EVW;
#pragma unroll
    for (int i = 0; i < (16 * EVW) / 256; i++) {
        int idx = tid + i * 256;      // coalesced in [d][e] layout
        float s = 0.f;
#pragma unroll
        for (int p = 0; p < NCHUNK; p++) s += g_kvp[p][base + idx];
        buf[idx] = s;
    }
    __syncthreads();
    __half* oh = g_kvTh + (size_t)bh * EVW * HD + q * 16;
#pragma unroll
    for (int i = 0; i < (16 * EVW) / 256; i++) {
        int idx = tid + i * 256;
        int e = idx >> 4, d = idx & 15;
        oh[e * HD + d] = __float2half_rn(buf[d * EVW + e]);
    }
}

// ---------------- k_attn: 128-row tiles, out = Q @ kvT^T, single pass -------
__global__ __launch_bounds__(128) void k_attn() {
    __shared__ char sm[128 * KSTR + EVW * KSTR];
    const uint32_t sQ = smem_u32(sm);
    const uint32_t sH = sQ + 128 * KSTR;
    const int bh = blockIdx.x;
    const int tile = blockIdx.y;
    const int tid = threadIdx.x;
    const int lane = tid & 31;
    const int warp = tid >> 5;

    const __half* Qg = g_Q16 + ((size_t)bh * NN + tile * 128) * HD;
    const __half* Hg = g_kvTh + (size_t)bh * EVW * HD;

#pragma unroll
    for (int i = 0; i < 8; i++) {
        int idx = tid + i * 128;
        int r = idx >> 3, c = idx & 7;
        cp16(sQ + r * KSTR + c * 16, Qg + r * HD + c * 8);
    }
#pragma unroll
    for (int i = 0; i < 5; i++) {
        int idx = tid + i * 128;
        int r = idx >> 3, c = idx & 7;
        cp16(sH + r * KSTR + c * 16, Hg + r * HD + c * 8);
    }
    CP_COMMIT();
    CP_WAIT(0);
    __syncthreads();

    float acc[2][10][4];
#pragma unroll
    for (int m = 0; m < 2; m++)
#pragma unroll
        for (int i = 0; i < 10; i++)
#pragma unroll
            for (int j = 0; j < 4; j++) acc[m][i][j] = 0.f;

    const int grp = lane >> 3;
    const uint32_t a_off0 = (uint32_t)(warp * 32 + (lane & 15)) * KSTR + ((lane >> 4) * 8) * 2;
    const uint32_t b_off0 = (uint32_t)(((grp & 2) << 2) + (lane & 7)) * KSTR + ((grp & 1) * 8) * 2;

#pragma unroll
    for (int kk = 0; kk < 4; kk++) {
        uint32_t a[2][4];
#pragma unroll
        for (int mt = 0; mt < 2; mt++)
            LDSM4(a[mt], sQ + a_off0 + (uint32_t)mt * 16 * KSTR + kk * 32);
#pragma unroll
        for (int eb = 0; eb < 5; eb++) {
            uint32_t b[4];
            LDSM4(b, sH + b_off0 + (uint32_t)(16 * eb) * KSTR + kk * 32);
#pragma unroll
            for (int mt = 0; mt < 2; mt++) {
                mma16816(acc[mt][2 * eb], a[mt], b);
                mma16816(acc[mt][2 * eb + 1], a[mt], b + 2);
            }
        }
    }

    const int b_ = bh >> 3, h = bh & 7;
#pragma unroll
    for (int mt = 0; mt < 2; mt++) {
        float d0v = __shfl_sync(0xffffffffu, acc[mt][8][0], lane & ~3);
        float d1v = __shfl_sync(0xffffffffu, acc[mt][8][2], lane & ~3);
        float z0 = 1.f / fmaxf(d0v, 1e-4f);
        float z1 = 1.f / fmaxf(d1v, 1e-4f);
        const int n0g = tile * 128 + warp * 32 + mt * 16 + (lane >> 2);
        __half* o = g_AT16 + ((size_t)(b_ * NN) + n0g) * INNER + h * HD;
#pragma unroll
        for (int nt = 0; nt < 8; nt++) {
            int col = nt * 8 + 2 * (lane & 3);
            *(__half2*)(o + col) = __floats2half2_rn(acc[mt][nt][0] * z0, acc[mt][nt][1] * z0);
            *(__half2*)(o + 8 * INNER + col) =
                __floats2half2_rn(acc[mt][nt][2] * z1, acc[mt][nt][3] * z1);
        }
    }
}

// ---------------- launch ----------------
extern "C" void kernel_launch(void* const* d_in, const int* in_sizes, int n_in,
                              void* d_out, int out_size) {
    const float* x = (const float*)d_in[0];
    const float* W_qkv = (const float*)d_in[1];
    const float* W_out = (const float*)d_in[2];
    const float* b_out = (const float*)d_in[3];
    float* out = (float*)d_out;

    static int attr_done = 0;
    if (!attr_done) {
        cudaFuncSetAttribute((const void*)k_gemm_mma<1>,
                             cudaFuncAttributeMaxDynamicSharedMemorySize, SMEM_T);
        cudaFuncSetAttribute((const void*)k_gemm_mma<2>,
                             cudaFuncAttributeMaxDynamicSharedMemorySize, SMEM_T);
        attr_done = 1;
    }

    int n4_total = N4_X + N4_W1 + N4_W2;
    k_convert<<<(n4_total + 255) / 256, 256>>>((const float4*)x, (const float4*)W_qkv,
                                               (const float4*)W_out);

    dim3 g1(1536 / 128, MTOT / 128);
    k_gemm_mma<1><<<g1, 256, SMEM_T>>>(nullptr, nullptr);

    dim3 g2(BHH, NCHUNK);
    k_kv<<<g2, 128>>>();

    dim3 gr(BHH, 4);
    k_reduce<<<gr, 256>>>();

    dim3 g3(BHH, NN / 128);
    k_attn<<<g3, 128>>>();

    dim3 g4(INNER / 128, MTOT / 128);
    k_gemm_mma<2><<<g4, 256, SMEM_T>>>(b_out, out);
}

// round 15
// speedup vs baseline: 1.1516x; 1.0001x over previous
#include <cuda_runtime.h>
#include <cuda_fp16.h>
#include <math.h>
#include <stdint.h>

#define BB    16
#define NN    4096
#define DIMK  512
#define NH    8
#define HD    64
#define INNER 512
#define MTOT  (BB * NN)   // 65536
#define BHH   (BB * NH)   // 128
#define EVW   80          // kv columns: 64 V + 1 ones(ksum) + 15 pad
#define NCHUNK 8

// ---------------- scratch ----------------
__device__ __align__(256) __half g_Q16[(size_t)BHH * NN * HD];
__device__ __align__(256) __half g_K16[(size_t)BHH * NN * HD];
__device__ __align__(256) __half g_V16[(size_t)BHH * NN * HD];
__device__ __align__(256) __half g_X16[(size_t)MTOT * DIMK];
__device__ __align__(256) __half g_AT16[(size_t)MTOT * INNER];
__device__ __align__(256) __half g_W1[1536 * DIMK];
__device__ __align__(256) __half g_W2[INNER * INNER];
__device__ float g_kvp[NCHUNK][BHH * HD * EVW];
__device__ __align__(256) __half g_kvTh[BHH * EVW * HD];   // [bh][e][d]

// ---------------- helpers ----------------
__device__ __forceinline__ uint32_t smem_u32(const void* p) {
    uint32_t a;
    asm("{ .reg .u64 t; cvta.to.shared.u64 t, %1; cvt.u32.u64 %0, t; }" : "=r"(a) : "l"(p));
    return a;
}
__device__ __forceinline__ void cp16(uint32_t dst, const void* src) {
    asm volatile("cp.async.cg.shared.global [%0], [%1], 16;" ::
                 "r"(dst), "l"(__cvta_generic_to_global(src)) : "memory");
}
#define CP_COMMIT() asm volatile("cp.async.commit_group;" ::: "memory")
#define CP_WAIT(n)  asm volatile("cp.async.wait_group %0;" :: "n"(n) : "memory")

#define LDSM4(R, A)                                                              \
    asm volatile("ldmatrix.sync.aligned.m8n8.x4.shared.b16 {%0,%1,%2,%3}, [%4];" \
                 : "=r"((R)[0]), "=r"((R)[1]), "=r"((R)[2]), "=r"((R)[3])        \
                 : "r"(A))
#define LDSM4T(R, A)                                                                   \
    asm volatile("ldmatrix.sync.aligned.m8n8.x4.trans.shared.b16 {%0,%1,%2,%3}, [%4];" \
                 : "=r"((R)[0]), "=r"((R)[1]), "=r"((R)[2]), "=r"((R)[3])              \
                 : "r"(A))

__device__ __forceinline__ void mma16816(float* c, const uint32_t* a, const uint32_t* b) {
    asm volatile(
        "mma.sync.aligned.m16n8k16.row.col.f32.f16.f16.f32 "
        "{%0,%1,%2,%3}, {%4,%5,%6,%7}, {%8,%9}, {%0,%1,%2,%3};"
        : "+f"(c[0]), "+f"(c[1]), "+f"(c[2]), "+f"(c[3])
        : "r"(a[0]), "r"(a[1]), "r"(a[2]), "r"(a[3]), "r"(b[0]), "r"(b[1]));
}

// ---------------- fused convert fp32 -> fp16 ----------------
#define N4_X  (MTOT * DIMK / 4)
#define N4_W1 (1536 * DIMK / 4)
#define N4_W2 (INNER * INNER / 4)
__global__ void k_convert(const float4* __restrict__ x, const float4* __restrict__ w1,
                          const float4* __restrict__ w2) {
    int i = blockIdx.x * 256 + threadIdx.x;
    const float4* src;
    uint2* dst;
    int j = i;
    if (i < N4_X) {
        src = x; dst = (uint2*)g_X16;
    } else if (i < N4_X + N4_W1) {
        j = i - N4_X; src = w1; dst = (uint2*)g_W1;
    } else if (i < N4_X + N4_W1 + N4_W2) {
        j = i - N4_X - N4_W1; src = w2; dst = (uint2*)g_W2;
    } else {
        return;
    }
    float4 v = src[j];
    uint2 H;
    H.x = (uint32_t)__half_as_ushort(__float2half_rn(v.x)) |
          ((uint32_t)__half_as_ushort(__float2half_rn(v.y)) << 16);
    H.y = (uint32_t)__half_as_ushort(__float2half_rn(v.z)) |
          ((uint32_t)__half_as_ushort(__float2half_rn(v.w)) << 16);
    dst[j] = H;
}

// ---------------- fp16 GEMM: 256 thr, warp 32x64, LDSM/MMA software pipeline --
#define ROWB 144
#define ASZ  (128 * ROWB)
#define STAGE_SZ (2 * ASZ)
#define SMEM_T (3 * STAGE_SZ)

template <int GEMM_ID>
__global__ __launch_bounds__(256, 2) void k_gemm_mma(const float* __restrict__ bias,
                                                     float* __restrict__ outp) {
    extern __shared__ char smem[];
    const uint32_t sb = smem_u32(smem);
    const int tid = threadIdx.x;
    const int lane = tid & 31;
    const int wid = tid >> 5;
    const int warp_m = wid >> 1;
    const int warp_n = wid & 1;
    const int m0 = blockIdx.y * 128;
    const int n0 = blockIdx.x * 128;

    const __half* A = (GEMM_ID == 1) ? g_X16 : g_AT16;
    const __half* B = (GEMM_ID == 1) ? g_W1 : g_W2;
    const int KD = (GEMM_ID == 1) ? DIMK : INNER;

    float acc[2][8][4];
#pragma unroll
    for (int i = 0; i < 2; i++)
#pragma unroll
        for (int j = 0; j < 8; j++)
#pragma unroll
            for (int k = 0; k < 4; k++) acc[i][j][k] = 0.f;

    const int lr = tid >> 3;
    const int lc = tid & 7;
    const uint32_t so_base = (uint32_t)lr * ROWB + lc * 16;
    const __half* gA = A + (size_t)(m0 + lr) * KD + lc * 8;
    const __half* gB = B + (size_t)(n0 + lr) * KD + lc * 8;

    auto load_stage = [&](uint32_t st, int k0) {
#pragma unroll
        for (int i = 0; i < 4; i++) {
            uint32_t so = so_base + (uint32_t)i * 32 * ROWB;
            cp16(st + so,       gA + (size_t)(i * 32) * KD + k0);
            cp16(st + ASZ + so, gB + (size_t)(i * 32) * KD + k0);
        }
        CP_COMMIT();
    };

    load_stage(sb, 0);
    load_stage(sb + STAGE_SZ, 64);

    uint32_t cur = sb;
    uint32_t nxt2 = sb + 2 * STAGE_SZ;

    const int arow = warp_m * 32 + (lane & 15);
    const int grp = lane >> 3;
    const int brow_l = warp_n * 64 + ((grp & 2) << 2) + (lane & 7);
    const uint32_t a_off0 = (uint32_t)arow * ROWB + ((lane >> 4) * 8) * 2;
    const uint32_t b_off0 = (uint32_t)brow_l * ROWB + ((grp & 1) * 8) * 2;

    // small double buffers: A per-kk (2x 8 regs), B per-np (2x 4 regs)
    uint32_t ah[2][2][4];   // [buf][mt][4]
    uint32_t bb[2][4];      // [buf][4]

#pragma unroll 1
    for (int s = 0; s < 8; s++) {
        if (s < 7) { CP_WAIT(1); } else { CP_WAIT(0); }
        __syncthreads();
        if (s < 6) {
            load_stage(nxt2, (s + 2) * 64);
            nxt2 += STAGE_SZ;
            if (nxt2 == sb + 3 * STAGE_SZ) nxt2 = sb;
        }
        const uint32_t aT = cur, bT = cur + ASZ;

        // stage prologue: kk=0 A frags + first B frag
#pragma unroll
        for (int mt = 0; mt < 2; mt++)
            LDSM4(ah[0][mt], aT + a_off0 + (uint32_t)mt * 16 * ROWB);
        LDSM4(bb[0], bT + b_off0);

#pragma unroll
        for (int kk = 0; kk < 4; kk++) {
            const int cbA = kk & 1;
            const int nbA = cbA ^ 1;
            if (kk < 3) {  // prefetch next kk's A fragments
#pragma unroll
                for (int mt = 0; mt < 2; mt++)
                    LDSM4(ah[nbA][mt],
                          aT + a_off0 + (uint32_t)mt * 16 * ROWB + (kk + 1) * 32);
            }
#pragma unroll
            for (int np = 0; np < 4; np++) {
                const int cbB = np & 1;
                const int nbB = cbB ^ 1;
                // prefetch next B fragment (next np, or np=0 of next kk)
                if (np < 3) {
                    LDSM4(bb[nbB], bT + b_off0 + (uint32_t)(np + 1) * 16 * ROWB + kk * 32);
                } else if (kk < 3) {
                    LDSM4(bb[nbB], bT + b_off0 + (kk + 1) * 32);
                }
#pragma unroll
                for (int half = 0; half < 2; half++) {
                    const int nt = np * 2 + half;
                    uint32_t bhf[2] = {bb[cbB][half * 2], bb[cbB][half * 2 + 1]};
#pragma unroll
                    for (int mt = 0; mt < 2; mt++)
                        mma16816(acc[mt][nt], ah[cbA][mt], bhf);
                }
            }
        }
        cur += STAGE_SZ;
        if (cur == sb + 3 * STAGE_SZ) cur = sb;
    }

    // ---------------- epilogue ----------------
    const int r0 = lane >> 2;
    const int c0 = (lane & 3) * 2;
#pragma unroll
    for (int mt = 0; mt < 2; mt++) {
#pragma unroll
        for (int nt = 0; nt < 8; nt++) {
            const int col = n0 + warp_n * 64 + nt * 8 + c0;
#pragma unroll
            for (int ri = 0; ri < 2; ri++) {
                const int m = m0 + warp_m * 32 + mt * 16 + r0 + ri * 8;
                float v0 = acc[mt][nt][ri * 2];
                float v1 = acc[mt][nt][ri * 2 + 1];
                if (GEMM_ID == 1) {
                    const int which = col >> 9;
                    const int h = (col >> 6) & 7;
                    const int dd = col & 63;
                    __half* dst = (which == 0) ? g_Q16 : (which == 1) ? g_K16 : g_V16;
                    if (which < 2) {
                        v0 = (v0 > 0.f) ? v0 + 1.f : expf(v0);
                        v1 = (v1 > 0.f) ? v1 + 1.f : expf(v1);
                    }
                    const int b_ = m >> 12, n_ = m & 4095;
                    *(__half2*)(dst + ((size_t)(b_ * NH + h) * NN + n_) * HD + dd) =
                        __floats2half2_rn(v0, v1);
                } else {
                    *(float2*)(outp + (size_t)m * INNER + col) =
                        make_float2(v0 + __ldg(bias + col), v1 + __ldg(bias + col + 1));
                }
            }
        }
    }
}

// ---------------- k_kv: MMA, C[64d x 80e'] = K^T [V|1|0], 8 chunks ----------
#define KSTR 144
#define VSTR 176
#define KTILE (64 * KSTR)
#define VTILE (64 * VSTR)
#define CHROWS (NN / NCHUNK)   // 512

__global__ __launch_bounds__(128) void k_kv() {
    __shared__ char sm[2 * KTILE + 2 * VTILE];
    const uint32_t sK = smem_u32(sm);
    const uint32_t sV = sK + 2 * KTILE;
    const int bh = blockIdx.x;
    const int chunk = blockIdx.y;
    const int tid = threadIdx.x;
    const int lane = tid & 31;
    const int warp = tid >> 5;

    const __half* Kg = g_K16 + ((size_t)bh * NN + chunk * CHROWS) * HD;
    const __half* Vg = g_V16 + ((size_t)bh * NN + chunk * CHROWS) * HD;

    {
        int r = tid & 63, buf = tid >> 6;
        uint32_t base = sV + buf * VTILE + r * VSTR + 128;
        *(uint4*)(sm + (base - sK)) = make_uint4(0x00003c00u, 0u, 0u, 0u);
        *(uint4*)(sm + (base - sK) + 16) = make_uint4(0u, 0u, 0u, 0u);
    }

    auto load = [&](int buf, int t) {
        const __half* kp = Kg + (size_t)t * 64 * HD;
        const __half* vp = Vg + (size_t)t * 64 * HD;
#pragma unroll
        for (int i = 0; i < 4; i++) {
            int idx = tid + i * 128;
            int r = idx >> 3, c = idx & 7;
            cp16(sK + buf * KTILE + r * KSTR + c * 16, kp + r * HD + c * 8);
            cp16(sV + buf * VTILE + r * VSTR + c * 16, vp + r * HD + c * 8);
        }
        CP_COMMIT();
    };

    float acc[10][4];
#pragma unroll
    for (int i = 0; i < 10; i++)
#pragma unroll
        for (int j = 0; j < 4; j++) acc[i][j] = 0.f;

    const int i7 = lane & 7;
    const int s4 = lane >> 3;
    const uint32_t aoff = (uint32_t)(i7 + ((s4 >> 1) << 3)) * KSTR +
                          (16 * warp + ((s4 & 1) << 3)) * 2;
    const uint32_t boff = (uint32_t)(i7 + ((s4 & 1) << 3)) * VSTR + ((s4 >> 1) << 3) * 2;

    load(0, 0);
#pragma unroll 1
    for (int t = 0; t < CHROWS / 64; t++) {
        if (t < CHROWS / 64 - 1) load((t + 1) & 1, t + 1);
        if (t < CHROWS / 64 - 1) { CP_WAIT(1); } else { CP_WAIT(0); }
        __syncthreads();
        const uint32_t kb = sK + (t & 1) * KTILE;
        const uint32_t vb = sV + (t & 1) * VTILE;
#pragma unroll
        for (int n0 = 0; n0 < 64; n0 += 16) {
            uint32_t a[4];
            LDSM4T(a, kb + aoff + n0 * KSTR);
#pragma unroll
            for (int eb = 0; eb < 5; eb++) {
                uint32_t b[4];
                LDSM4T(b, vb + boff + n0 * VSTR + eb * 32);
                mma16816(acc[2 * eb], a, b);
                mma16816(acc[2 * eb + 1], a, b + 2);
            }
        }
        __syncthreads();
    }

    float* o = g_kvp[chunk] + (size_t)bh * HD * EVW;
    const int d0 = 16 * warp + (lane >> 2);
    const int e0 = 2 * (lane & 3);
#pragma unroll
    for (int nt = 0; nt < 10; nt++) {
        int e = nt * 8 + e0;
        *(float2*)(o + d0 * EVW + e) = make_float2(acc[nt][0], acc[nt][1]);
        *(float2*)(o + (d0 + 8) * EVW + e) = make_float2(acc[nt][2], acc[nt][3]);
    }
}

// ---------------- reduce partials -> kvT fp16 [bh][e][d], 4-way d split ------
__global__ __launch_bounds__(256) void k_reduce() {
    __shared__ float buf[16 * EVW];   // 5 KB
    const int bh = blockIdx.x;
    const int q = blockIdx.y;
    const int tid = threadIdx.x;
    const size_t base = (size_t)bh * HD * EVW + (size_t)q * 16 * EVW;
#pragma unroll
    for (int i = 0; i < (16 * EVW) / 256; i++) {
        int idx = tid + i * 256;
        float s = 0.f;
#pragma unroll
        for (int p = 0; p < NCHUNK; p++) s += g_kvp[p][base + idx];
        buf[idx] = s;
    }
    __syncthreads();
    __half* oh = g_kvTh + (size_t)bh * EVW * HD + q * 16;
#pragma unroll
    for (int i = 0; i < (16 * EVW) / 256; i++) {
        int idx = tid + i * 256;
        int e = idx >> 4, d = idx & 15;
        oh[e * HD + d] = __float2half_rn(buf[d * EVW + e]);
    }
}

// ---------------- k_attn: 128-row tiles, out = Q @ kvT^T, single pass -------
__global__ __launch_bounds__(128) void k_attn() {
    __shared__ char sm[128 * KSTR + EVW * KSTR];
    const uint32_t sQ = smem_u32(sm);
    const uint32_t sH = sQ + 128 * KSTR;
    const int bh = blockIdx.x;
    const int tile = blockIdx.y;
    const int tid = threadIdx.x;
    const int lane = tid & 31;
    const int warp = tid >> 5;

    const __half* Qg = g_Q16 + ((size_t)bh * NN + tile * 128) * HD;
    const __half* Hg = g_kvTh + (size_t)bh * EVW * HD;

#pragma unroll
    for (int i = 0; i < 8; i++) {
        int idx = tid + i * 128;
        int r = idx >> 3, c = idx & 7;
        cp16(sQ + r * KSTR + c * 16, Qg + r * HD + c * 8);
    }
#pragma unroll
    for (int i = 0; i < 5; i++) {
        int idx = tid + i * 128;
        int r = idx >> 3, c = idx & 7;
        cp16(sH + r * KSTR + c * 16, Hg + r * HD + c * 8);
    }
    CP_COMMIT();
    CP_WAIT(0);
    __syncthreads();

    float acc[2][10][4];
#pragma unroll
    for (int m = 0; m < 2; m++)
#pragma unroll
        for (int i = 0; i < 10; i++)
#pragma unroll
            for (int j = 0; j < 4; j++) acc[m][i][j] = 0.f;

    const int grp = lane >> 3;
    const uint32_t a_off0 = (uint32_t)(warp * 32 + (lane & 15)) * KSTR + ((lane >> 4) * 8) * 2;
    const uint32_t b_off0 = (uint32_t)(((grp & 2) << 2) + (lane & 7)) * KSTR + ((grp & 1) * 8) * 2;

#pragma unroll
    for (int kk = 0; kk < 4; kk++) {
        uint32_t a[2][4];
#pragma unroll
        for (int mt = 0; mt < 2; mt++)
            LDSM4(a[mt], sQ + a_off0 + (uint32_t)mt * 16 * KSTR + kk * 32);
#pragma unroll
        for (int eb = 0; eb < 5; eb++) {
            uint32_t b[4];
            LDSM4(b, sH + b_off0 + (uint32_t)(16 * eb) * KSTR + kk * 32);
#pragma unroll
            for (int mt = 0; mt < 2; mt++) {
                mma16816(acc[mt][2 * eb], a[mt], b);
                mma16816(acc[mt][2 * eb + 1], a[mt], b + 2);
            }
        }
    }

    const int b_ = bh >> 3, h = bh & 7;
#pragma unroll
    for (int mt = 0; mt < 2; mt++) {
        float d0v = __shfl_sync(0xffffffffu, acc[mt][8][0], lane & ~3);
        float d1v = __shfl_sync(0xffffffffu, acc[mt][8][2], lane & ~3);
        float z0 = 1.f / fmaxf(d0v, 1e-4f);
        float z1 = 1.f / fmaxf(d1v, 1e-4f);
        const int n0g = tile * 128 + warp * 32 + mt * 16 + (lane >> 2);
        __half* o = g_AT16 + ((size_t)(b_ * NN) + n0g) * INNER + h * HD;
#pragma unroll
        for (int nt = 0; nt < 8; nt++) {
            int col = nt * 8 + 2 * (lane & 3);
            *(__half2*)(o + col) = __floats2half2_rn(acc[mt][nt][0] * z0, acc[mt][nt][1] * z0);
            *(__half2*)(o + 8 * INNER + col) =
                __floats2half2_rn(acc[mt][nt][2] * z1, acc[mt][nt][3] * z1);
        }
    }
}

// ---------------- launch ----------------
extern "C" void kernel_launch(void* const* d_in, const int* in_sizes, int n_in,
                              void* d_out, int out_size) {
    const float* x = (const float*)d_in[0];
    const float* W_qkv = (const float*)d_in[1];
    const float* W_out = (const float*)d_in[2];
    const float* b_out = (const float*)d_in[3];
    float* out = (float*)d_out;

    static int attr_done = 0;
    if (!attr_done) {
        cudaFuncSetAttribute((const void*)k_gemm_mma<1>,
                             cudaFuncAttributeMaxDynamicSharedMemorySize, SMEM_T);
        cudaFuncSetAttribute((const void*)k_gemm_mma<2>,
                             cudaFuncAttributeMaxDynamicSharedMemorySize, SMEM_T);
        attr_done = 1;
    }

    int n4_total = N4_X + N4_W1 + N4_W2;
    k_convert<<<(n4_total + 255) / 256, 256>>>((const float4*)x, (const float4*)W_qkv,
                                               (const float4*)W_out);

    dim3 g1(1536 / 128, MTOT / 128);
    k_gemm_mma<1><<<g1, 256, SMEM_T>>>(nullptr, nullptr);

    dim3 g2(BHH, NCHUNK);
    k_kv<<<g2, 128>>>();

    dim3 gr(BHH, 4);
    k_reduce<<<gr, 256>>>();

    dim3 g3(BHH, NN / 128);
    k_attn<<<g3, 128>>>();

    dim3 g4(INNER / 128, MTOT / 128);
    k_gemm_mma<2><<<g4, 256, SMEM_T>>>(b_out, out);
}